// round 7
// baseline (speedup 1.0000x reference)
#include <cuda_runtime.h>

#define NN 100000
#define EE 1200000
#define GG 512
#define IND 16
#define HD 64
#define BN_EPS 1e-5f
#define CSRCAP (EE + 3 * NN + 16)

// ---------------- scratch (static device globals; no allocation) ------------
__device__ int   g_deg[NN];
__device__ int   g_cursor[NN];
__device__ float g_dis[NN];
__device__ int   g_rowptr[NN + 1];
__device__ __align__(16) int   g_col[CSRCAP];
__device__ __align__(16) float g_cw[CSRCAP];
__device__ int   g_bsums[256];
__device__ int   g_boffs[256];
__device__ __align__(16) float g_agg16[NN * IND];
__device__ __align__(16) float g_bufs[3][NN * HD];
__device__ float g_stats[4 * 128];   // 3 used: [64 sums][64 sumsq] each
__device__ float g_stats_in[2 * IND];
__device__ float g_pool[GG * HD];
__device__ int   g_pcnt[GG];

// ---------------- f32x2 packed helpers --------------------------------------
__device__ __forceinline__ unsigned long long pack2(float lo, float hi) {
    unsigned long long r;
    asm("mov.b64 %0, {%1, %2};" : "=l"(r) : "f"(lo), "f"(hi));
    return r;
}
__device__ __forceinline__ void fma2(unsigned long long& d, unsigned long long a,
                                     unsigned long long b) {
    asm("fma.rn.f32x2 %0, %1, %2, %0;" : "+l"(d) : "l"(a), "l"(b));
}

// ---------------- init (also zeroes stats_in + cw pad insurance) ------------
__global__ void k_init() {
    int t0 = blockIdx.x * blockDim.x + threadIdx.x;
    int stride = gridDim.x * blockDim.x;
    for (int i = t0; i < NN; i += stride) { g_deg[i] = 1; g_cursor[i] = 0; }
    for (int i = t0; i < CSRCAP; i += stride) g_cw[i] = 0.f;
    for (int i = t0; i < 4 * 128; i += stride) g_stats[i] = 0.f;
    for (int i = t0; i < 2 * IND; i += stride) g_stats_in[i] = 0.f;
    for (int i = t0; i < GG * HD; i += stride) g_pool[i] = 0.f;
    for (int i = t0; i < GG; i += stride) g_pcnt[i] = 0;
}

// ---------------- degree (int4 edge reads) ----------------------------------
__global__ void k_deg(const int* __restrict__ ei) {
    const int4* d4 = (const int4*)(ei + EE);
    int t0 = blockIdx.x * blockDim.x + threadIdx.x;
    int stride = gridDim.x * blockDim.x;
    for (int e = t0; e < EE / 4; e += stride) {
        int4 v = d4[e];
        atomicAdd(&g_deg[v.x], 1);
        atomicAdd(&g_deg[v.y], 1);
        atomicAdd(&g_deg[v.z], 1);
        atomicAdd(&g_deg[v.w], 1);
    }
}

// ---------------- scan of PADDED edge counts (3-phase), fused dis -----------
// padded count per row = ((deg-1)+3) & ~3  -> every CSR row 4-aligned.
__global__ void k_scan1() {
    __shared__ int sm[512];
    int tid = threadIdx.x;
    int i = blockIdx.x * 512 + tid;
    int v = 0;
    if (i < NN) {
        int deg = g_deg[i];
        g_dis[i] = rsqrtf((float)deg);
        v = ((deg - 1) + 3) & ~3;
    }
    sm[tid] = v;
    __syncthreads();
    #pragma unroll
    for (int off = 1; off < 512; off <<= 1) {
        int t = (tid >= off) ? sm[tid - off] : 0;
        __syncthreads();
        sm[tid] += t;
        __syncthreads();
    }
    if (i < NN) g_rowptr[i] = sm[tid] - v;      // local exclusive
    if (tid == 511) g_bsums[blockIdx.x] = sm[511];
}

__global__ void k_scan2(int nb) {
    __shared__ int sm[256];
    int tid = threadIdx.x;
    int v = (tid < nb) ? g_bsums[tid] : 0;
    sm[tid] = v;
    __syncthreads();
    #pragma unroll
    for (int off = 1; off < 256; off <<= 1) {
        int t = (tid >= off) ? sm[tid - off] : 0;
        __syncthreads();
        sm[tid] += t;
        __syncthreads();
    }
    g_boffs[tid] = sm[tid] - v;                 // exclusive block offsets
    if (tid == nb - 1) g_rowptr[NN] = sm[tid];  // total padded count
}

__global__ void k_scan3() {
    int i = blockIdx.x * blockDim.x + threadIdx.x;
    if (i < NN) g_rowptr[i] += g_boffs[i >> 9];
}

// ---------------- CSR fill (int4 edge reads; pad slots stay cw=0) -----------
__global__ void k_fill(const int* __restrict__ ei) {
    const int4* s4 = (const int4*)ei;
    const int4* d4 = (const int4*)(ei + EE);
    int t0 = blockIdx.x * blockDim.x + threadIdx.x;
    int stride = gridDim.x * blockDim.x;
    for (int e = t0; e < EE / 4; e += stride) {
        int4 s = s4[e];
        int4 d = d4[e];
        int p;
        p = g_rowptr[d.x] + atomicAdd(&g_cursor[d.x], 1);
        g_col[p] = s.x; g_cw[p] = g_dis[s.x] * g_dis[d.x];
        p = g_rowptr[d.y] + atomicAdd(&g_cursor[d.y], 1);
        g_col[p] = s.y; g_cw[p] = g_dis[s.y] * g_dis[d.y];
        p = g_rowptr[d.z] + atomicAdd(&g_cursor[d.z], 1);
        g_col[p] = s.z; g_cw[p] = g_dis[s.z] * g_dis[d.z];
        p = g_rowptr[d.w] + atomicAdd(&g_cursor[d.w], 1);
        g_col[p] = s.w; g_cw[p] = g_dis[s.w] * g_dis[d.w];
    }
}

// ---------------- input BN stats (D=16 over raw x) --------------------------
__global__ void k_stats_in(const float* __restrict__ src) {
    __shared__ float ss[2 * IND];
    for (int t = threadIdx.x; t < 2 * IND; t += blockDim.x) ss[t] = 0.f;
    __syncthreads();
    float ls[IND], lq[IND];
    #pragma unroll
    for (int c = 0; c < IND; c++) { ls[c] = 0.f; lq[c] = 0.f; }
    int stride = gridDim.x * blockDim.x;
    for (int r = blockIdx.x * blockDim.x + threadIdx.x; r < NN; r += stride) {
        const float4* row = (const float4*)(src + r * IND);
        #pragma unroll
        for (int q = 0; q < IND / 4; q++) {
            float4 v = row[q];
            ls[4*q+0] += v.x; lq[4*q+0] += v.x * v.x;
            ls[4*q+1] += v.y; lq[4*q+1] += v.y * v.y;
            ls[4*q+2] += v.z; lq[4*q+2] += v.z * v.z;
            ls[4*q+3] += v.w; lq[4*q+3] += v.w * v.w;
        }
    }
    #pragma unroll
    for (int c = 0; c < IND; c++) {
        #pragma unroll
        for (int o = 16; o > 0; o >>= 1) {
            ls[c] += __shfl_xor_sync(0xffffffffu, ls[c], o);
            lq[c] += __shfl_xor_sync(0xffffffffu, lq[c], o);
        }
    }
    if ((threadIdx.x & 31) == 0) {
        #pragma unroll
        for (int c = 0; c < IND; c++) {
            atomicAdd(&ss[c], ls[c]);
            atomicAdd(&ss[IND + c], lq[c]);
        }
    }
    __syncthreads();
    for (int t = threadIdx.x; t < 2 * IND; t += blockDim.x) atomicAdd(&g_stats_in[t], ss[t]);
}

// ---------------- column stats over D=64 (coalesced float2) -----------------
__global__ void k_cstats(const float* __restrict__ src, float* __restrict__ stats) {
    __shared__ float ss[2 * HD];
    for (int t = threadIdx.x; t < 2 * HD; t += blockDim.x) ss[t] = 0.f;
    __syncthreads();
    int c2 = threadIdx.x & 31;                 // column pair
    int rpi = (blockDim.x / 32) * gridDim.x;   // rows per iteration
    int r0 = blockIdx.x * (blockDim.x / 32) + (threadIdx.x >> 5);
    const float2* s2 = (const float2*)src;
    float ls0 = 0.f, lq0 = 0.f, ls1 = 0.f, lq1 = 0.f;
    for (int r = r0; r < NN; r += rpi) {
        float2 v = s2[r * 32 + c2];
        ls0 += v.x; lq0 += v.x * v.x;
        ls1 += v.y; lq1 += v.y * v.y;
    }
    atomicAdd(&ss[2 * c2], ls0);
    atomicAdd(&ss[2 * c2 + 1], ls1);
    atomicAdd(&ss[HD + 2 * c2], lq0);
    atomicAdd(&ss[HD + 2 * c2 + 1], lq1);
    __syncthreads();
    for (int t = threadIdx.x; t < 2 * HD; t += blockDim.x) atomicAdd(&stats[t], ss[t]);
}

// ---------------- fused layer: agg(BN+ReLU on gather) + GEMM ----------------
// One warp per node. Gather phase: lane owns column pair; padded CSR rows let
// us read 4 cols with one int4 and 4 weights with one float4. GEMM phase:
// stage the aggregated 64-vector in shared, multiply against W (shared) with
// packed f32x2 FMAs. Output is raw (pre-BN); k_cstats runs on it next.
__global__ void __launch_bounds__(256) k_layer64(
    const float* __restrict__ hraw, const float* __restrict__ stats,
    const float* __restrict__ g, const float* __restrict__ be,
    const float* __restrict__ W, const float* __restrict__ b,
    float* __restrict__ out)
{
    __shared__ __align__(16) float sW[HD * HD];
    __shared__ __align__(16) float sB[HD];
    __shared__ __align__(16) float sA[8][HD];
    for (int t = threadIdx.x; t < HD * HD; t += 256) sW[t] = W[t];
    if (threadIdx.x < HD) sB[threadIdx.x] = b[threadIdx.x];
    __syncthreads();

    int wid = threadIdx.x >> 5, lane = threadIdx.x & 31;
    int node = blockIdx.x * 8 + wid;            // grid sized exactly NN/8

    const float invn = 1.0f / NN;
    int c0 = 2 * lane, c1 = 2 * lane + 1;
    float m0 = stats[c0] * invn, m1 = stats[c1] * invn;
    float v0 = stats[HD + c0] * invn - m0 * m0;
    float v1 = stats[HD + c1] * invn - m1 * m1;
    float sc0 = g[c0] * rsqrtf(v0 + BN_EPS), sc1 = g[c1] * rsqrtf(v1 + BN_EPS);
    float sh0 = be[c0] - m0 * sc0, sh1 = be[c1] - m1 * sc1;

    const float2* __restrict__ h2 = (const float2*)hraw;
    float di = g_dis[node];
    float2 hv = h2[node * 32 + lane];
    float ax = di * di * fmaxf(fmaf(hv.x, sc0, sh0), 0.f);
    float ay = di * di * fmaxf(fmaf(hv.y, sc1, sh1), 0.f);
    float bx = 0.f, by = 0.f;
    int s = g_rowptr[node], e = g_rowptr[node + 1];   // multiples of 4
    for (int p = s; p < e; p += 4) {
        int4   j4 = *(const int4*)(g_col + p);
        float4 c4 = *(const float4*)(g_cw + p);
        float2 w0 = h2[j4.x * 32 + lane];
        float2 w1 = h2[j4.y * 32 + lane];
        float2 w2 = h2[j4.z * 32 + lane];
        float2 w3 = h2[j4.w * 32 + lane];
        ax += c4.x * fmaxf(fmaf(w0.x, sc0, sh0), 0.f);
        ay += c4.x * fmaxf(fmaf(w0.y, sc1, sh1), 0.f);
        bx += c4.y * fmaxf(fmaf(w1.x, sc0, sh0), 0.f);
        by += c4.y * fmaxf(fmaf(w1.y, sc1, sh1), 0.f);
        ax += c4.z * fmaxf(fmaf(w2.x, sc0, sh0), 0.f);
        ay += c4.z * fmaxf(fmaf(w2.y, sc1, sh1), 0.f);
        bx += c4.w * fmaxf(fmaf(w3.x, sc0, sh0), 0.f);
        by += c4.w * fmaxf(fmaf(w3.y, sc1, sh1), 0.f);
    }
    *(float2*)&sA[wid][c0] = make_float2(ax + bx, ay + by);
    __syncwarp();

    unsigned long long acc = *(const unsigned long long*)&sB[c0];
    const unsigned long long* w2p = (const unsigned long long*)sW;
    #pragma unroll
    for (int k = 0; k < HD; k++) {
        float a = sA[wid][k];
        fma2(acc, pack2(a, a), w2p[k * 32 + lane]);
    }
    ((unsigned long long*)out)[node * 32 + lane] = acc;
}

// ---------------- agg over BN(x), D=16 (padded CSR, int4 col loads) ---------
// 4 nodes per warp, 8 lanes per node; lane owns column pair (2*fl, 2*fl+1).
__global__ void k_agg16p(const float* __restrict__ x, const float* __restrict__ bng,
                         const float* __restrict__ bnb, float* __restrict__ out) {
    int t = blockIdx.x * blockDim.x + threadIdx.x;
    int warp = t >> 5, lane = t & 31;
    int node = warp * 4 + (lane >> 3);
    int fl = lane & 7;
    if (node >= NN) return;
    const float invn = 1.0f / NN;
    int c0 = 2 * fl, c1 = 2 * fl + 1;
    float m0 = g_stats_in[c0] * invn, m1 = g_stats_in[c1] * invn;
    float v0 = g_stats_in[IND + c0] * invn - m0 * m0;
    float v1 = g_stats_in[IND + c1] * invn - m1 * m1;
    float sc0 = bng[c0] * rsqrtf(v0 + BN_EPS), sc1 = bng[c1] * rsqrtf(v1 + BN_EPS);
    float sh0 = bnb[c0] - m0 * sc0, sh1 = bnb[c1] - m1 * sc1;

    const float2* __restrict__ h2 = (const float2*)x;
    float di = g_dis[node];
    float2 hv = h2[node * 8 + fl];
    float ax = di * di * fmaf(hv.x, sc0, sh0);
    float ay = di * di * fmaf(hv.y, sc1, sh1);
    float bx = 0.f, by = 0.f;
    int s = g_rowptr[node], e = g_rowptr[node + 1];
    for (int p = s; p < e; p += 4) {
        int4   j4 = *(const int4*)(g_col + p);
        float4 c4 = *(const float4*)(g_cw + p);
        float2 w0 = h2[j4.x * 8 + fl];
        float2 w1 = h2[j4.y * 8 + fl];
        float2 w2 = h2[j4.z * 8 + fl];
        float2 w3 = h2[j4.w * 8 + fl];
        ax += c4.x * fmaf(w0.x, sc0, sh0);
        ay += c4.x * fmaf(w0.y, sc1, sh1);
        bx += c4.y * fmaf(w1.x, sc0, sh0);
        by += c4.y * fmaf(w1.y, sc1, sh1);
        ax += c4.z * fmaf(w2.x, sc0, sh0);
        ay += c4.z * fmaf(w2.y, sc1, sh1);
        bx += c4.w * fmaf(w3.x, sc0, sh0);
        by += c4.w * fmaf(w3.y, sc1, sh1);
    }
    ((float2*)out)[node * 8 + fl] = make_float2(ax + bx, ay + by);
}

// ---------------- dense matmul 16->64 (f32x2 packed FMA) --------------------
template <int CI>
__global__ void k_mm(const float* __restrict__ A, const float* __restrict__ W,
                     const float* __restrict__ b, float* __restrict__ out) {
    __shared__ __align__(16) float sW[CI * HD];
    __shared__ __align__(16) float sB[HD];
    for (int t = threadIdx.x; t < CI * HD; t += blockDim.x) sW[t] = W[t];
    for (int t = threadIdx.x; t < HD; t += blockDim.x) sB[t] = b[t];
    __syncthreads();
    int row = blockIdx.x * blockDim.x + threadIdx.x;
    if (row >= NN) return;
    unsigned long long acc[HD / 2];
    #pragma unroll
    for (int c = 0; c < HD / 2; c++)
        acc[c] = *(const unsigned long long*)&sB[2 * c];
    const float4* A4 = (const float4*)(A + row * CI);
    #pragma unroll
    for (int k0 = 0; k0 < CI; k0 += 4) {
        float4 a4 = A4[k0 / 4];
        float av[4] = {a4.x, a4.y, a4.z, a4.w};
        #pragma unroll
        for (int kk = 0; kk < 4; kk++) {
            unsigned long long xx = pack2(av[kk], av[kk]);
            const unsigned long long* wr =
                (const unsigned long long*)&sW[(k0 + kk) * HD];
            #pragma unroll
            for (int c = 0; c < HD / 2; c++) fma2(acc[c], xx, wr[c]);
        }
    }
    unsigned long long* o8 = (unsigned long long*)(out + row * HD);
    #pragma unroll
    for (int c = 0; c < HD / 2; c++) o8[c] = acc[c];
}

// ---------------- global mean pool with fused BN+ReLU -----------------------
__global__ void k_pool(const float* __restrict__ hraw, const float* __restrict__ stats,
                       const float* __restrict__ g, const float* __restrict__ be,
                       const int* __restrict__ bid) {
    int t = blockIdx.x * blockDim.x + threadIdx.x;
    int w = t >> 5, lane = t & 31;
    int base = w * 8;
    if (base >= NN) return;
    const float invn = 1.0f / NN;
    int c0 = 2 * lane, c1 = 2 * lane + 1;
    float m0 = stats[c0] * invn, m1 = stats[c1] * invn;
    float v0 = stats[HD + c0] * invn - m0 * m0;
    float v1 = stats[HD + c1] * invn - m1 * m1;
    float sc0 = g[c0] * rsqrtf(v0 + BN_EPS), sc1 = g[c1] * rsqrtf(v1 + BN_EPS);
    float sh0 = be[c0] - m0 * sc0, sh1 = be[c1] - m1 * sc1;

    const float2* h2 = (const float2*)hraw;
    float2 acc = make_float2(0.f, 0.f);
    int cur = -1, cnt = 0;
    for (int k = 0; k < 8; k++) {
        int i = base + k;
        if (i >= NN) break;
        int gr = bid[i];
        if (gr != cur) {
            if (cur >= 0) {
                atomicAdd(&g_pool[cur * HD + c0], acc.x);
                atomicAdd(&g_pool[cur * HD + c1], acc.y);
                if (lane == 0) atomicAdd(&g_pcnt[cur], cnt);
            }
            cur = gr; acc = make_float2(0.f, 0.f); cnt = 0;
        }
        float2 v = h2[i * 32 + lane];
        acc.x += fmaxf(fmaf(v.x, sc0, sh0), 0.f);
        acc.y += fmaxf(fmaf(v.y, sc1, sh1), 0.f);
        cnt++;
    }
    if (cur >= 0) {
        atomicAdd(&g_pool[cur * HD + c0], acc.x);
        atomicAdd(&g_pool[cur * HD + c1], acc.y);
        if (lane == 0) atomicAdd(&g_pcnt[cur], cnt);
    }
}

// ---------------- classifier head ------------------------------------------
__global__ void k_head(const float* __restrict__ Wc1, const float* __restrict__ bc1,
                       const float* __restrict__ Wc2, const float* __restrict__ bc2,
                       float* __restrict__ out) {
    __shared__ float sW[HD * HD];
    __shared__ float sb1[HD];
    __shared__ float sW2[HD * 2];
    __shared__ float sb2[2];
    for (int t = threadIdx.x; t < HD * HD; t += blockDim.x) sW[t] = Wc1[t];
    for (int t = threadIdx.x; t < HD; t += blockDim.x) sb1[t] = bc1[t];
    for (int t = threadIdx.x; t < HD * 2; t += blockDim.x) sW2[t] = Wc2[t];
    if (threadIdx.x < 2) sb2[threadIdx.x] = bc2[threadIdx.x];
    __syncthreads();
    int g = blockIdx.x * blockDim.x + threadIdx.x;
    if (g >= GG) return;
    float cnt = fmaxf((float)g_pcnt[g], 1.0f);
    float inv = 1.0f / cnt;
    float p[HD];
    #pragma unroll
    for (int f = 0; f < HD; f++) p[f] = g_pool[g * HD + f] * inv;
    float o0 = sb2[0], o1 = sb2[1];
    #pragma unroll 8
    for (int c = 0; c < HD; c++) {
        float z = sb1[c];
        #pragma unroll
        for (int k = 0; k < HD; k++) z += p[k] * sW[k * HD + c];
        z = fmaxf(z, 0.f);
        o0 += z * sW2[c * 2];
        o1 += z * sW2[c * 2 + 1];
    }
    out[g * 2] = o0;
    out[g * 2 + 1] = o1;
}

// ---------------- launch ----------------------------------------------------
extern "C" void kernel_launch(void* const* d_in, const int* in_sizes, int n_in,
                              void* d_out, int out_size) {
    const float *x, *bng, *bnb, *W0, *b0, *g0, *be0, *W1, *b1, *g1, *be1;
    const float *W2, *b2, *g2, *be2, *Wc1, *bc1, *Wc2, *bc2;
    const int *ei, *bid;

    if (in_sizes[1] == 2 * EE) {
        x   = (const float*)d_in[0];  ei  = (const int*)d_in[1];  bid = (const int*)d_in[2];
        bng = (const float*)d_in[3];  bnb = (const float*)d_in[4];
        W0  = (const float*)d_in[5];  b0  = (const float*)d_in[6];
        g0  = (const float*)d_in[7];  be0 = (const float*)d_in[8];
        W1  = (const float*)d_in[9];  b1  = (const float*)d_in[10];
        g1  = (const float*)d_in[11]; be1 = (const float*)d_in[12];
        W2  = (const float*)d_in[13]; b2  = (const float*)d_in[14];
        g2  = (const float*)d_in[15]; be2 = (const float*)d_in[16];
        Wc1 = (const float*)d_in[17]; bc1 = (const float*)d_in[18];
        Wc2 = (const float*)d_in[19]; bc2 = (const float*)d_in[20];
    } else {
        x   = (const float*)d_in[0];
        bng = (const float*)d_in[1];  bnb = (const float*)d_in[2];
        W0  = (const float*)d_in[3];  b0  = (const float*)d_in[4];
        g0  = (const float*)d_in[5];  be0 = (const float*)d_in[6];
        W1  = (const float*)d_in[7];  b1  = (const float*)d_in[8];
        g1  = (const float*)d_in[9];  be1 = (const float*)d_in[10];
        W2  = (const float*)d_in[11]; b2  = (const float*)d_in[12];
        g2  = (const float*)d_in[13]; be2 = (const float*)d_in[14];
        Wc1 = (const float*)d_in[15]; bc1 = (const float*)d_in[16];
        Wc2 = (const float*)d_in[17]; bc2 = (const float*)d_in[18];
        ei  = (const int*)d_in[19];   bid = (const int*)d_in[20];
    }

    float *bufs, *a16, *st;
    cudaGetSymbolAddress((void**)&bufs, g_bufs);
    cudaGetSymbolAddress((void**)&a16, g_agg16);
    cudaGetSymbolAddress((void**)&st, g_stats);
    float *B0 = bufs, *B1 = bufs + NN * HD, *B2 = bufs + 2 * NN * HD;
    float *S1 = st, *S2 = st + 128, *S3 = st + 256;
    float* out = (float*)d_out;

    const int nb_scan1 = (NN + 511) / 512;    // 196
    const int nb_n = (NN + 255) / 256;
    const int nb_edge = (EE / 4 + 255) / 256; // 1172
    const int nb_agg16 = (((NN + 3) / 4) * 32 + 255) / 256;
    const int nb_mm = (NN + 127) / 128;
    const int nb_l64 = NN / 8;                // 12500, exact
    const int nb_pool = (((NN + 7) / 8) * 32 + 255) / 256;

    // ---- graph build + input stats ----
    k_init<<<2048, 256>>>();                              // 0
    k_stats_in<<<256, 256>>>(x);                          // 1
    k_deg<<<nb_edge, 256>>>(ei);                          // 2
    k_scan1<<<nb_scan1, 512>>>();                         // 3  <- ncu capture
    k_scan2<<<1, 256>>>(nb_scan1);                        // 4
    k_scan3<<<nb_n, 256>>>();                             // 5
    k_fill<<<nb_edge, 256>>>(ei);                         // 6

    // ---- layer 0 (16 -> 64): agg over BN(x), mm, stats ----
    k_agg16p<<<nb_agg16, 256>>>(x, bng, bnb, a16);        // 7
    k_mm<IND><<<nb_mm, 128>>>(a16, W0, b0, B0);           // 8
    k_cstats<<<256, 256>>>(B0, S1);                       // 9

    // ---- layer 1 (64 -> 64): fused agg(BN0+relu) + GEMM ----
    k_layer64<<<nb_l64, 256>>>(B0, S1, g0, be0, W1, b1, B1);  // 10
    k_cstats<<<256, 256>>>(B1, S2);                           // 11

    // ---- layer 2 (64 -> 64): fused agg(BN1+relu) + GEMM ----
    k_layer64<<<nb_l64, 256>>>(B1, S2, g1, be1, W2, b2, B2);  // 12
    k_cstats<<<256, 256>>>(B2, S3);                           // 13

    // ---- pool (applies BN2+relu) + head ----
    k_pool<<<nb_pool, 256>>>(B2, S3, g2, be2, bid);       // 14
    k_head<<<(GG + 63) / 64, 64>>>(Wc1, bc1, Wc2, bc2, out); // 15
}

// round 8
// speedup vs baseline: 1.1100x; 1.1100x over previous
#include <cuda_runtime.h>

#define NN 100000
#define EE 1200000
#define GG 512
#define IND 16
#define HD 64
#define BN_EPS 1e-5f

// ---------------- scratch (static device globals; no allocation) ------------
__device__ int   g_deg[NN];
__device__ int   g_cursor[NN];
__device__ float g_dis[NN];
__device__ int   g_rowptr[NN + 1];
__device__ int   g_col[EE];
__device__ float g_cw[EE];
__device__ int   g_bsums[256];
__device__ int   g_boffs[256];
__device__ __align__(16) float g_agg16[NN * IND];
__device__ __align__(16) float g_bufs[3][NN * HD];
__device__ float g_stats[4 * 128];   // 3 used: [64 sums][64 sumsq] each
__device__ float g_stats_in[2 * IND];
__device__ float g_pool[GG * HD];
__device__ int   g_pcnt[GG];

// ---------------- f32x2 packed helpers --------------------------------------
__device__ __forceinline__ unsigned long long pack2(float lo, float hi) {
    unsigned long long r;
    asm("mov.b64 %0, {%1, %2};" : "=l"(r) : "f"(lo), "f"(hi));
    return r;
}
__device__ __forceinline__ void fma2(unsigned long long& d, unsigned long long a,
                                     unsigned long long b) {
    asm("fma.rn.f32x2 %0, %1, %2, %0;" : "+l"(d) : "l"(a), "l"(b));
}

// ---------------- init ------------------------------------------------------
__global__ void k_init() {
    int t0 = blockIdx.x * blockDim.x + threadIdx.x;
    int stride = gridDim.x * blockDim.x;
    for (int i = t0; i < NN; i += stride) { g_deg[i] = 1; g_cursor[i] = 0; }
    for (int i = t0; i < 4 * 128; i += stride) g_stats[i] = 0.f;
    for (int i = t0; i < GG * HD; i += stride) g_pool[i] = 0.f;
    for (int i = t0; i < GG; i += stride) g_pcnt[i] = 0;
    if (t0 == 0) g_rowptr[NN] = EE;
}

__global__ void k_zero_in() {
    if (threadIdx.x < 2 * IND) g_stats_in[threadIdx.x] = 0.f;
}

// ---------------- degree (int4 edge reads) ----------------------------------
__global__ void k_deg(const int* __restrict__ ei) {
    const int4* d4 = (const int4*)(ei + EE);
    int t0 = blockIdx.x * blockDim.x + threadIdx.x;
    int stride = gridDim.x * blockDim.x;
    for (int e = t0; e < EE / 4; e += stride) {
        int4 v = d4[e];
        atomicAdd(&g_deg[v.x], 1);
        atomicAdd(&g_deg[v.y], 1);
        atomicAdd(&g_deg[v.z], 1);
        atomicAdd(&g_deg[v.w], 1);
    }
}

// ---------------- exclusive scan of indegree (3-phase), fused dis -----------
__global__ void k_scan1() {
    __shared__ int sm[512];
    int tid = threadIdx.x;
    int i = blockIdx.x * 512 + tid;
    int v = (i < NN) ? (g_deg[i] - 1) : 0;
    if (i < NN) g_dis[i] = rsqrtf((float)(v + 1));
    sm[tid] = v;
    __syncthreads();
    #pragma unroll
    for (int off = 1; off < 512; off <<= 1) {
        int t = (tid >= off) ? sm[tid - off] : 0;
        __syncthreads();
        sm[tid] += t;
        __syncthreads();
    }
    if (i < NN) g_rowptr[i] = sm[tid] - v;      // local exclusive
    if (tid == 511) g_bsums[blockIdx.x] = sm[511];
}

__global__ void k_scan2(int nb) {
    __shared__ int sm[256];
    int tid = threadIdx.x;
    int v = (tid < nb) ? g_bsums[tid] : 0;
    sm[tid] = v;
    __syncthreads();
    #pragma unroll
    for (int off = 1; off < 256; off <<= 1) {
        int t = (tid >= off) ? sm[tid - off] : 0;
        __syncthreads();
        sm[tid] += t;
        __syncthreads();
    }
    g_boffs[tid] = sm[tid] - v;                 // exclusive block offsets
}

__global__ void k_scan3() {
    int i = blockIdx.x * blockDim.x + threadIdx.x;
    if (i < NN) g_rowptr[i] += g_boffs[i >> 9];
}

// ---------------- CSR fill (int4 edge reads) --------------------------------
__global__ void k_fill(const int* __restrict__ ei) {
    const int4* s4 = (const int4*)ei;
    const int4* d4 = (const int4*)(ei + EE);
    int t0 = blockIdx.x * blockDim.x + threadIdx.x;
    int stride = gridDim.x * blockDim.x;
    for (int e = t0; e < EE / 4; e += stride) {
        int4 s = s4[e];
        int4 d = d4[e];
        int p;
        p = g_rowptr[d.x] + atomicAdd(&g_cursor[d.x], 1);
        g_col[p] = s.x; g_cw[p] = g_dis[s.x] * g_dis[d.x];
        p = g_rowptr[d.y] + atomicAdd(&g_cursor[d.y], 1);
        g_col[p] = s.y; g_cw[p] = g_dis[s.y] * g_dis[d.y];
        p = g_rowptr[d.z] + atomicAdd(&g_cursor[d.z], 1);
        g_col[p] = s.z; g_cw[p] = g_dis[s.z] * g_dis[d.z];
        p = g_rowptr[d.w] + atomicAdd(&g_cursor[d.w], 1);
        g_col[p] = s.w; g_cw[p] = g_dis[s.w] * g_dis[d.w];
    }
}

// ---------------- input BN stats (D=16 over raw x) --------------------------
__global__ void k_stats_in(const float* __restrict__ src) {
    __shared__ float ss[2 * IND];
    for (int t = threadIdx.x; t < 2 * IND; t += blockDim.x) ss[t] = 0.f;
    __syncthreads();
    float ls[IND], lq[IND];
    #pragma unroll
    for (int c = 0; c < IND; c++) { ls[c] = 0.f; lq[c] = 0.f; }
    int stride = gridDim.x * blockDim.x;
    for (int r = blockIdx.x * blockDim.x + threadIdx.x; r < NN; r += stride) {
        const float4* row = (const float4*)(src + r * IND);
        #pragma unroll
        for (int q = 0; q < IND / 4; q++) {
            float4 v = row[q];
            ls[4*q+0] += v.x; lq[4*q+0] += v.x * v.x;
            ls[4*q+1] += v.y; lq[4*q+1] += v.y * v.y;
            ls[4*q+2] += v.z; lq[4*q+2] += v.z * v.z;
            ls[4*q+3] += v.w; lq[4*q+3] += v.w * v.w;
        }
    }
    #pragma unroll
    for (int c = 0; c < IND; c++) {
        #pragma unroll
        for (int o = 16; o > 0; o >>= 1) {
            ls[c] += __shfl_xor_sync(0xffffffffu, ls[c], o);
            lq[c] += __shfl_xor_sync(0xffffffffu, lq[c], o);
        }
    }
    if ((threadIdx.x & 31) == 0) {
        #pragma unroll
        for (int c = 0; c < IND; c++) {
            atomicAdd(&ss[c], ls[c]);
            atomicAdd(&ss[IND + c], lq[c]);
        }
    }
    __syncthreads();
    for (int t = threadIdx.x; t < 2 * IND; t += blockDim.x) atomicAdd(&g_stats_in[t], ss[t]);
}

// ---------------- column stats over D=64 (coalesced float2) -----------------
__global__ void k_cstats(const float* __restrict__ src, float* __restrict__ stats) {
    __shared__ float ss[2 * HD];
    for (int t = threadIdx.x; t < 2 * HD; t += blockDim.x) ss[t] = 0.f;
    __syncthreads();
    int c2 = threadIdx.x & 31;                 // column pair
    int rpi = (blockDim.x / 32) * gridDim.x;   // rows per iteration
    int r0 = blockIdx.x * (blockDim.x / 32) + (threadIdx.x >> 5);
    const float2* s2 = (const float2*)src;
    float ls0 = 0.f, lq0 = 0.f, ls1 = 0.f, lq1 = 0.f;
    for (int r = r0; r < NN; r += rpi) {
        float2 v = s2[r * 32 + c2];
        ls0 += v.x; lq0 += v.x * v.x;
        ls1 += v.y; lq1 += v.y * v.y;
    }
    atomicAdd(&ss[2 * c2], ls0);
    atomicAdd(&ss[2 * c2 + 1], ls1);
    atomicAdd(&ss[HD + 2 * c2], lq0);
    atomicAdd(&ss[HD + 2 * c2 + 1], lq1);
    __syncthreads();
    for (int t = threadIdx.x; t < 2 * HD; t += blockDim.x) atomicAdd(&stats[t], ss[t]);
}

// ---------------- aggregation with fused BN(+ReLU) on gathered loads --------
// D=64: one warp per node, each lane owns column pair (2*lane, 2*lane+1).
__global__ void k_agg64(const float* __restrict__ hraw, const float* __restrict__ stats,
                        const float* __restrict__ g, const float* __restrict__ be,
                        float* __restrict__ out) {
    int t = blockIdx.x * blockDim.x + threadIdx.x;
    int node = t >> 5, lane = t & 31;
    if (node >= NN) return;
    const float invn = 1.0f / NN;
    int c0 = 2 * lane, c1 = 2 * lane + 1;
    float m0 = stats[c0] * invn, m1 = stats[c1] * invn;
    float v0 = stats[HD + c0] * invn - m0 * m0;
    float v1 = stats[HD + c1] * invn - m1 * m1;
    float sc0 = g[c0] * rsqrtf(v0 + BN_EPS), sc1 = g[c1] * rsqrtf(v1 + BN_EPS);
    float sh0 = be[c0] - m0 * sc0, sh1 = be[c1] - m1 * sc1;

    const float2* __restrict__ h2 = (const float2*)hraw;
    float di = g_dis[node];
    float2 hv = h2[node * 32 + lane];
    float t0 = fmaxf(fmaf(hv.x, sc0, sh0), 0.f);
    float t1 = fmaxf(fmaf(hv.y, sc1, sh1), 0.f);
    float ax = di * di * t0, ay = di * di * t1;
    float bx = 0.f, by = 0.f;
    int s = g_rowptr[node], e = g_rowptr[node + 1];
    int p = s;
    for (; p + 4 <= e; p += 4) {
        int j0 = g_col[p], j1 = g_col[p + 1], j2 = g_col[p + 2], j3 = g_col[p + 3];
        float c0w = g_cw[p], c1w = g_cw[p + 1], c2w = g_cw[p + 2], c3w = g_cw[p + 3];
        float2 w0 = h2[j0 * 32 + lane];
        float2 w1 = h2[j1 * 32 + lane];
        float2 w2 = h2[j2 * 32 + lane];
        float2 w3 = h2[j3 * 32 + lane];
        ax += c0w * fmaxf(fmaf(w0.x, sc0, sh0), 0.f);
        ay += c0w * fmaxf(fmaf(w0.y, sc1, sh1), 0.f);
        bx += c1w * fmaxf(fmaf(w1.x, sc0, sh0), 0.f);
        by += c1w * fmaxf(fmaf(w1.y, sc1, sh1), 0.f);
        ax += c2w * fmaxf(fmaf(w2.x, sc0, sh0), 0.f);
        ay += c2w * fmaxf(fmaf(w2.y, sc1, sh1), 0.f);
        bx += c3w * fmaxf(fmaf(w3.x, sc0, sh0), 0.f);
        by += c3w * fmaxf(fmaf(w3.y, sc1, sh1), 0.f);
    }
    for (; p < e; p++) {
        int j = g_col[p];
        float cw = g_cw[p];
        float2 w = h2[j * 32 + lane];
        ax += cw * fmaxf(fmaf(w.x, sc0, sh0), 0.f);
        ay += cw * fmaxf(fmaf(w.y, sc1, sh1), 0.f);
    }
    ((float2*)out)[node * 32 + lane] = make_float2(ax + bx, ay + by);
}

// D=16 over raw x with fused input-BN affine. 4 nodes/warp, 8 lanes/node.
__global__ void k_agg16p(const float* __restrict__ x, const float* __restrict__ bng,
                         const float* __restrict__ bnb, float* __restrict__ out) {
    int t = blockIdx.x * blockDim.x + threadIdx.x;
    int warp = t >> 5, lane = t & 31;
    int node = warp * 4 + (lane >> 3);
    int fl = lane & 7;
    if (node >= NN) return;
    const float invn = 1.0f / NN;
    int c0 = 2 * fl, c1 = 2 * fl + 1;
    float m0 = g_stats_in[c0] * invn, m1 = g_stats_in[c1] * invn;
    float v0 = g_stats_in[IND + c0] * invn - m0 * m0;
    float v1 = g_stats_in[IND + c1] * invn - m1 * m1;
    float sc0 = bng[c0] * rsqrtf(v0 + BN_EPS), sc1 = bng[c1] * rsqrtf(v1 + BN_EPS);
    float sh0 = bnb[c0] - m0 * sc0, sh1 = bnb[c1] - m1 * sc1;

    const float2* __restrict__ h2 = (const float2*)x;
    float di = g_dis[node];
    float2 hv = h2[node * 8 + fl];
    float ax = di * di * fmaf(hv.x, sc0, sh0);
    float ay = di * di * fmaf(hv.y, sc1, sh1);
    float bx = 0.f, by = 0.f;
    int s = g_rowptr[node], e = g_rowptr[node + 1];
    int p = s;
    for (; p + 4 <= e; p += 4) {
        int j0 = g_col[p], j1 = g_col[p + 1], j2 = g_col[p + 2], j3 = g_col[p + 3];
        float c0w = g_cw[p], c1w = g_cw[p + 1], c2w = g_cw[p + 2], c3w = g_cw[p + 3];
        float2 w0 = h2[j0 * 8 + fl];
        float2 w1 = h2[j1 * 8 + fl];
        float2 w2 = h2[j2 * 8 + fl];
        float2 w3 = h2[j3 * 8 + fl];
        ax += c0w * fmaf(w0.x, sc0, sh0);
        ay += c0w * fmaf(w0.y, sc1, sh1);
        bx += c1w * fmaf(w1.x, sc0, sh0);
        by += c1w * fmaf(w1.y, sc1, sh1);
        ax += c2w * fmaf(w2.x, sc0, sh0);
        ay += c2w * fmaf(w2.y, sc1, sh1);
        bx += c3w * fmaf(w3.x, sc0, sh0);
        by += c3w * fmaf(w3.y, sc1, sh1);
    }
    for (; p < e; p++) {
        int j = g_col[p];
        float cw = g_cw[p];
        float2 w = h2[j * 8 + fl];
        ax += cw * fmaf(w.x, sc0, sh0);
        ay += cw * fmaf(w.y, sc1, sh1);
    }
    ((float2*)out)[node * 8 + fl] = make_float2(ax + bx, ay + by);
}

// ---------------- dense matmul (f32x2 packed FMA) ---------------------------
template <int CI>
__global__ void k_mm(const float* __restrict__ A, const float* __restrict__ W,
                     const float* __restrict__ b, float* __restrict__ out) {
    __shared__ __align__(16) float sW[CI * HD];
    __shared__ __align__(16) float sB[HD];
    for (int t = threadIdx.x; t < CI * HD; t += blockDim.x) sW[t] = W[t];
    for (int t = threadIdx.x; t < HD; t += blockDim.x) sB[t] = b[t];
    __syncthreads();
    int row = blockIdx.x * blockDim.x + threadIdx.x;
    if (row >= NN) return;
    unsigned long long acc[HD / 2];
    #pragma unroll
    for (int c = 0; c < HD / 2; c++)
        acc[c] = *(const unsigned long long*)&sB[2 * c];
    const float4* A4 = (const float4*)(A + row * CI);
    #pragma unroll
    for (int k0 = 0; k0 < CI; k0 += 4) {
        float4 a4 = A4[k0 / 4];
        float av[4] = {a4.x, a4.y, a4.z, a4.w};
        #pragma unroll
        for (int kk = 0; kk < 4; kk++) {
            unsigned long long xx = pack2(av[kk], av[kk]);
            const unsigned long long* wr =
                (const unsigned long long*)&sW[(k0 + kk) * HD];
            #pragma unroll
            for (int c = 0; c < HD / 2; c++) fma2(acc[c], xx, wr[c]);
        }
    }
    unsigned long long* o8 = (unsigned long long*)(out + row * HD);
    #pragma unroll
    for (int c = 0; c < HD / 2; c++) o8[c] = acc[c];
}

// ---------------- global mean pool with fused BN+ReLU -----------------------
__global__ void k_pool(const float* __restrict__ hraw, const float* __restrict__ stats,
                       const float* __restrict__ g, const float* __restrict__ be,
                       const int* __restrict__ bid) {
    int t = blockIdx.x * blockDim.x + threadIdx.x;
    int w = t >> 5, lane = t & 31;
    int base = w * 8;
    if (base >= NN) return;
    const float invn = 1.0f / NN;
    int c0 = 2 * lane, c1 = 2 * lane + 1;
    float m0 = stats[c0] * invn, m1 = stats[c1] * invn;
    float v0 = stats[HD + c0] * invn - m0 * m0;
    float v1 = stats[HD + c1] * invn - m1 * m1;
    float sc0 = g[c0] * rsqrtf(v0 + BN_EPS), sc1 = g[c1] * rsqrtf(v1 + BN_EPS);
    float sh0 = be[c0] - m0 * sc0, sh1 = be[c1] - m1 * sc1;

    const float2* h2 = (const float2*)hraw;
    float2 acc = make_float2(0.f, 0.f);
    int cur = -1, cnt = 0;
    for (int k = 0; k < 8; k++) {
        int i = base + k;
        if (i >= NN) break;
        int gr = bid[i];
        if (gr != cur) {
            if (cur >= 0) {
                atomicAdd(&g_pool[cur * HD + c0], acc.x);
                atomicAdd(&g_pool[cur * HD + c1], acc.y);
                if (lane == 0) atomicAdd(&g_pcnt[cur], cnt);
            }
            cur = gr; acc = make_float2(0.f, 0.f); cnt = 0;
        }
        float2 v = h2[i * 32 + lane];
        acc.x += fmaxf(fmaf(v.x, sc0, sh0), 0.f);
        acc.y += fmaxf(fmaf(v.y, sc1, sh1), 0.f);
        cnt++;
    }
    if (cur >= 0) {
        atomicAdd(&g_pool[cur * HD + c0], acc.x);
        atomicAdd(&g_pool[cur * HD + c1], acc.y);
        if (lane == 0) atomicAdd(&g_pcnt[cur], cnt);
    }
}

// ---------------- classifier head ------------------------------------------
__global__ void k_head(const float* __restrict__ Wc1, const float* __restrict__ bc1,
                       const float* __restrict__ Wc2, const float* __restrict__ bc2,
                       float* __restrict__ out) {
    __shared__ float sW[HD * HD];
    __shared__ float sb1[HD];
    __shared__ float sW2[HD * 2];
    __shared__ float sb2[2];
    for (int t = threadIdx.x; t < HD * HD; t += blockDim.x) sW[t] = Wc1[t];
    for (int t = threadIdx.x; t < HD; t += blockDim.x) sb1[t] = bc1[t];
    for (int t = threadIdx.x; t < HD * 2; t += blockDim.x) sW2[t] = Wc2[t];
    if (threadIdx.x < 2) sb2[threadIdx.x] = bc2[threadIdx.x];
    __syncthreads();
    int g = blockIdx.x * blockDim.x + threadIdx.x;
    if (g >= GG) return;
    float cnt = fmaxf((float)g_pcnt[g], 1.0f);
    float inv = 1.0f / cnt;
    float p[HD];
    #pragma unroll
    for (int f = 0; f < HD; f++) p[f] = g_pool[g * HD + f] * inv;
    float o0 = sb2[0], o1 = sb2[1];
    #pragma unroll 8
    for (int c = 0; c < HD; c++) {
        float z = sb1[c];
        #pragma unroll
        for (int k = 0; k < HD; k++) z += p[k] * sW[k * HD + c];
        z = fmaxf(z, 0.f);
        o0 += z * sW2[c * 2];
        o1 += z * sW2[c * 2 + 1];
    }
    out[g * 2] = o0;
    out[g * 2 + 1] = o1;
}

// ---------------- launch ----------------------------------------------------
extern "C" void kernel_launch(void* const* d_in, const int* in_sizes, int n_in,
                              void* d_out, int out_size) {
    const float *x, *bng, *bnb, *W0, *b0, *g0, *be0, *W1, *b1, *g1, *be1;
    const float *W2, *b2, *g2, *be2, *Wc1, *bc1, *Wc2, *bc2;
    const int *ei, *bid;

    if (in_sizes[1] == 2 * EE) {
        x   = (const float*)d_in[0];  ei  = (const int*)d_in[1];  bid = (const int*)d_in[2];
        bng = (const float*)d_in[3];  bnb = (const float*)d_in[4];
        W0  = (const float*)d_in[5];  b0  = (const float*)d_in[6];
        g0  = (const float*)d_in[7];  be0 = (const float*)d_in[8];
        W1  = (const float*)d_in[9];  b1  = (const float*)d_in[10];
        g1  = (const float*)d_in[11]; be1 = (const float*)d_in[12];
        W2  = (const float*)d_in[13]; b2  = (const float*)d_in[14];
        g2  = (const float*)d_in[15]; be2 = (const float*)d_in[16];
        Wc1 = (const float*)d_in[17]; bc1 = (const float*)d_in[18];
        Wc2 = (const float*)d_in[19]; bc2 = (const float*)d_in[20];
    } else {
        x   = (const float*)d_in[0];
        bng = (const float*)d_in[1];  bnb = (const float*)d_in[2];
        W0  = (const float*)d_in[3];  b0  = (const float*)d_in[4];
        g0  = (const float*)d_in[5];  be0 = (const float*)d_in[6];
        W1  = (const float*)d_in[7];  b1  = (const float*)d_in[8];
        g1  = (const float*)d_in[9];  be1 = (const float*)d_in[10];
        W2  = (const float*)d_in[11]; b2  = (const float*)d_in[12];
        g2  = (const float*)d_in[13]; be2 = (const float*)d_in[14];
        Wc1 = (const float*)d_in[15]; bc1 = (const float*)d_in[16];
        Wc2 = (const float*)d_in[17]; bc2 = (const float*)d_in[18];
        ei  = (const int*)d_in[19];   bid = (const int*)d_in[20];
    }

    float *bufs, *a16, *st;
    cudaGetSymbolAddress((void**)&bufs, g_bufs);
    cudaGetSymbolAddress((void**)&a16, g_agg16);
    cudaGetSymbolAddress((void**)&st, g_stats);
    float *B0 = bufs, *B1 = bufs + NN * HD, *B2 = bufs + 2 * NN * HD;
    float *S1 = st, *S2 = st + 128, *S3 = st + 256;
    float* out = (float*)d_out;

    const int nb_scan1 = (NN + 511) / 512;
    const int nb_n = (NN + 255) / 256;
    const int nb_edge = (EE / 4 + 255) / 256; // 1172
    const int nb_agg64 = (NN * 32 + 255) / 256;
    const int nb_agg16 = (((NN + 3) / 4) * 32 + 255) / 256;
    const int nb_mm = (NN + 127) / 128;
    const int nb_pool = (((NN + 7) / 8) * 32 + 255) / 256;

    // ---- graph build + input stats ----
    k_zero_in<<<1, 32>>>();                               // 0
    k_stats_in<<<256, 256>>>(x);                          // 1
    k_init<<<256, 256>>>();                               // 2
    k_deg<<<nb_edge, 256>>>(ei);                          // 3  <- ncu capture
    k_scan1<<<nb_scan1, 512>>>();                         // 4  (also computes dis)
    k_scan2<<<1, 256>>>(nb_scan1);                        // 5
    k_scan3<<<nb_n, 256>>>();                             // 6
    k_fill<<<nb_edge, 256>>>(ei);                         // 7

    // ---- layer 0 (16 -> 64): agg over BN(x), mm, stats ----
    k_agg16p<<<nb_agg16, 256>>>(x, bng, bnb, a16);        // 8
    k_mm<IND><<<nb_mm, 128>>>(a16, W0, b0, B0);           // 9
    k_cstats<<<256, 256>>>(B0, S1);                       // 10

    // ---- layer 1 (64 -> 64): agg applies BN0+relu on gathered loads ----
    k_agg64<<<nb_agg64, 256>>>(B0, S1, g0, be0, B1);      // 11
    k_mm<HD><<<nb_mm, 128>>>(B1, W1, b1, B2);             // 12
    k_cstats<<<256, 256>>>(B2, S2);                       // 13

    // ---- layer 2 (64 -> 64): agg applies BN1+relu ----
    k_agg64<<<nb_agg64, 256>>>(B2, S2, g1, be1, B1);      // 14
    k_mm<HD><<<nb_mm, 128>>>(B1, W2, b2, B0);             // 15
    k_cstats<<<256, 256>>>(B0, S3);                       // 16

    // ---- pool (applies BN2+relu) + head ----
    k_pool<<<nb_pool, 256>>>(B0, S3, g2, be2, bid);       // 17
    k_head<<<(GG + 63) / 64, 64>>>(Wc1, bc1, Wc2, bc2, out); // 18
}

// round 9
// speedup vs baseline: 1.2360x; 1.1136x over previous
#include <cuda_runtime.h>
#include <cuda_fp16.h>

#define NN 100000
#define EE 1200000
#define GG 512
#define IND 16
#define HD 64
#define BN_EPS 1e-5f

// ---------------- scratch (static device globals; no allocation) ------------
__device__ int   g_deg[NN];
__device__ int   g_cursor[NN];
__device__ float g_dis[NN];
__device__ int   g_rowptr[NN + 1];
__device__ int   g_col[EE];
__device__ float g_cw[EE];
__device__ int   g_bsums[256];
__device__ int   g_boffs[256];
__device__ __align__(16) float  g_agg16[NN * IND];
__device__ __align__(16) float  g_D[NN * HD];          // fp32 agg64 output
__device__ __align__(16) __half g_H[2][NN * HD];       // fp16 layer outputs
__device__ float g_stats[4 * 128];   // 3 used: [64 sums][64 sumsq] each
__device__ float g_stats_in[2 * IND];
__device__ float g_pool[GG * HD];
__device__ int   g_pcnt[GG];

// ---------------- f32x2 / half helpers ---------------------------------------
__device__ __forceinline__ unsigned long long pack2(float lo, float hi) {
    unsigned long long r;
    asm("mov.b64 %0, {%1, %2};" : "=l"(r) : "f"(lo), "f"(hi));
    return r;
}
__device__ __forceinline__ void fma2(unsigned long long& d, unsigned long long a,
                                     unsigned long long b) {
    asm("fma.rn.f32x2 %0, %1, %2, %0;" : "+l"(d) : "l"(a), "l"(b));
}
__device__ __forceinline__ float lo32(unsigned long long v) {
    return __uint_as_float((unsigned)v);
}
__device__ __forceinline__ float hi32(unsigned long long v) {
    return __uint_as_float((unsigned)(v >> 32));
}
__device__ __forceinline__ unsigned h2u(float lo, float hi) {
    __half2 h = __floats2half2_rn(lo, hi);
    return *(unsigned*)&h;
}

// ---------------- init (zeroes everything incl. stats_in) -------------------
__global__ void k_init() {
    int t0 = blockIdx.x * blockDim.x + threadIdx.x;
    int stride = gridDim.x * blockDim.x;
    for (int i = t0; i < NN; i += stride) { g_deg[i] = 1; g_cursor[i] = 0; }
    for (int i = t0; i < 4 * 128; i += stride) g_stats[i] = 0.f;
    for (int i = t0; i < 2 * IND; i += stride) g_stats_in[i] = 0.f;
    for (int i = t0; i < GG * HD; i += stride) g_pool[i] = 0.f;
    for (int i = t0; i < GG; i += stride) g_pcnt[i] = 0;
    if (t0 == 0) g_rowptr[NN] = EE;
}

// ---------------- degree (int4 edge reads) ----------------------------------
__global__ void k_deg(const int* __restrict__ ei) {
    const int4* d4 = (const int4*)(ei + EE);
    int t0 = blockIdx.x * blockDim.x + threadIdx.x;
    int stride = gridDim.x * blockDim.x;
    for (int e = t0; e < EE / 4; e += stride) {
        int4 v = d4[e];
        atomicAdd(&g_deg[v.x], 1);
        atomicAdd(&g_deg[v.y], 1);
        atomicAdd(&g_deg[v.z], 1);
        atomicAdd(&g_deg[v.w], 1);
    }
}

// ---------------- exclusive scan of indegree (3-phase), fused dis -----------
__global__ void k_scan1() {
    __shared__ int sm[512];
    int tid = threadIdx.x;
    int i = blockIdx.x * 512 + tid;
    int v = (i < NN) ? (g_deg[i] - 1) : 0;
    if (i < NN) g_dis[i] = rsqrtf((float)(v + 1));
    sm[tid] = v;
    __syncthreads();
    #pragma unroll
    for (int off = 1; off < 512; off <<= 1) {
        int t = (tid >= off) ? sm[tid - off] : 0;
        __syncthreads();
        sm[tid] += t;
        __syncthreads();
    }
    if (i < NN) g_rowptr[i] = sm[tid] - v;      // local exclusive
    if (tid == 511) g_bsums[blockIdx.x] = sm[511];
}

__global__ void k_scan2(int nb) {
    __shared__ int sm[256];
    int tid = threadIdx.x;
    int v = (tid < nb) ? g_bsums[tid] : 0;
    sm[tid] = v;
    __syncthreads();
    #pragma unroll
    for (int off = 1; off < 256; off <<= 1) {
        int t = (tid >= off) ? sm[tid - off] : 0;
        __syncthreads();
        sm[tid] += t;
        __syncthreads();
    }
    g_boffs[tid] = sm[tid] - v;                 // exclusive block offsets
}

__global__ void k_scan3() {
    int i = blockIdx.x * blockDim.x + threadIdx.x;
    if (i < NN) g_rowptr[i] += g_boffs[i >> 9];
}

// ---------------- CSR fill (int4 edge reads) --------------------------------
__global__ void k_fill(const int* __restrict__ ei) {
    const int4* s4 = (const int4*)ei;
    const int4* d4 = (const int4*)(ei + EE);
    int t0 = blockIdx.x * blockDim.x + threadIdx.x;
    int stride = gridDim.x * blockDim.x;
    for (int e = t0; e < EE / 4; e += stride) {
        int4 s = s4[e];
        int4 d = d4[e];
        int p;
        p = g_rowptr[d.x] + atomicAdd(&g_cursor[d.x], 1);
        g_col[p] = s.x; g_cw[p] = g_dis[s.x] * g_dis[d.x];
        p = g_rowptr[d.y] + atomicAdd(&g_cursor[d.y], 1);
        g_col[p] = s.y; g_cw[p] = g_dis[s.y] * g_dis[d.y];
        p = g_rowptr[d.z] + atomicAdd(&g_cursor[d.z], 1);
        g_col[p] = s.z; g_cw[p] = g_dis[s.z] * g_dis[d.z];
        p = g_rowptr[d.w] + atomicAdd(&g_cursor[d.w], 1);
        g_col[p] = s.w; g_cw[p] = g_dis[s.w] * g_dis[d.w];
    }
}

// ---------------- input BN stats (D=16 over raw x) --------------------------
__global__ void k_stats_in(const float* __restrict__ src) {
    __shared__ float ss[2 * IND];
    for (int t = threadIdx.x; t < 2 * IND; t += blockDim.x) ss[t] = 0.f;
    __syncthreads();
    float ls[IND], lq[IND];
    #pragma unroll
    for (int c = 0; c < IND; c++) { ls[c] = 0.f; lq[c] = 0.f; }
    int stride = gridDim.x * blockDim.x;
    for (int r = blockIdx.x * blockDim.x + threadIdx.x; r < NN; r += stride) {
        const float4* row = (const float4*)(src + r * IND);
        #pragma unroll
        for (int q = 0; q < IND / 4; q++) {
            float4 v = row[q];
            ls[4*q+0] += v.x; lq[4*q+0] += v.x * v.x;
            ls[4*q+1] += v.y; lq[4*q+1] += v.y * v.y;
            ls[4*q+2] += v.z; lq[4*q+2] += v.z * v.z;
            ls[4*q+3] += v.w; lq[4*q+3] += v.w * v.w;
        }
    }
    #pragma unroll
    for (int c = 0; c < IND; c++) {
        #pragma unroll
        for (int o = 16; o > 0; o >>= 1) {
            ls[c] += __shfl_xor_sync(0xffffffffu, ls[c], o);
            lq[c] += __shfl_xor_sync(0xffffffffu, lq[c], o);
        }
    }
    if ((threadIdx.x & 31) == 0) {
        #pragma unroll
        for (int c = 0; c < IND; c++) {
            atomicAdd(&ss[c], ls[c]);
            atomicAdd(&ss[IND + c], lq[c]);
        }
    }
    __syncthreads();
    for (int t = threadIdx.x; t < 2 * IND; t += blockDim.x) atomicAdd(&g_stats_in[t], ss[t]);
}

// ---------------- column stats over D=64 (half2 input) ----------------------
__global__ void k_cstats(const __half2* __restrict__ src, float* __restrict__ stats) {
    __shared__ float ss[2 * HD];
    for (int t = threadIdx.x; t < 2 * HD; t += blockDim.x) ss[t] = 0.f;
    __syncthreads();
    int c2 = threadIdx.x & 31;                 // column pair
    int rpi = (blockDim.x / 32) * gridDim.x;   // rows per iteration
    int r0 = blockIdx.x * (blockDim.x / 32) + (threadIdx.x >> 5);
    float ls0 = 0.f, lq0 = 0.f, ls1 = 0.f, lq1 = 0.f;
    for (int r = r0; r < NN; r += rpi) {
        float2 v = __half22float2(src[r * 32 + c2]);
        ls0 += v.x; lq0 += v.x * v.x;
        ls1 += v.y; lq1 += v.y * v.y;
    }
    atomicAdd(&ss[2 * c2], ls0);
    atomicAdd(&ss[2 * c2 + 1], ls1);
    atomicAdd(&ss[HD + 2 * c2], lq0);
    atomicAdd(&ss[HD + 2 * c2 + 1], lq1);
    __syncthreads();
    for (int t = threadIdx.x; t < 2 * HD; t += blockDim.x) atomicAdd(&stats[t], ss[t]);
}

// ---------------- aggregation: gather half2, fused BN+ReLU, fp32 math -------
// D=64: one warp per node, each lane owns column pair (2*lane, 2*lane+1).
__global__ void k_agg64(const __half2* __restrict__ hh, const float* __restrict__ stats,
                        const float* __restrict__ g, const float* __restrict__ be,
                        float* __restrict__ out) {
    int t = blockIdx.x * blockDim.x + threadIdx.x;
    int node = t >> 5, lane = t & 31;
    if (node >= NN) return;
    const float invn = 1.0f / NN;
    int c0 = 2 * lane, c1 = 2 * lane + 1;
    float m0 = stats[c0] * invn, m1 = stats[c1] * invn;
    float v0 = stats[HD + c0] * invn - m0 * m0;
    float v1 = stats[HD + c1] * invn - m1 * m1;
    float sc0 = g[c0] * rsqrtf(v0 + BN_EPS), sc1 = g[c1] * rsqrtf(v1 + BN_EPS);
    float sh0 = be[c0] - m0 * sc0, sh1 = be[c1] - m1 * sc1;

    float di = g_dis[node];
    float2 hv = __half22float2(hh[node * 32 + lane]);
    float ax = di * di * fmaxf(fmaf(hv.x, sc0, sh0), 0.f);
    float ay = di * di * fmaxf(fmaf(hv.y, sc1, sh1), 0.f);
    float bx = 0.f, by = 0.f;
    int s = g_rowptr[node], e = g_rowptr[node + 1];
    int p = s;
    for (; p + 4 <= e; p += 4) {
        int j0 = g_col[p], j1 = g_col[p + 1], j2 = g_col[p + 2], j3 = g_col[p + 3];
        float c0w = g_cw[p], c1w = g_cw[p + 1], c2w = g_cw[p + 2], c3w = g_cw[p + 3];
        float2 w0 = __half22float2(hh[j0 * 32 + lane]);
        float2 w1 = __half22float2(hh[j1 * 32 + lane]);
        float2 w2 = __half22float2(hh[j2 * 32 + lane]);
        float2 w3 = __half22float2(hh[j3 * 32 + lane]);
        ax += c0w * fmaxf(fmaf(w0.x, sc0, sh0), 0.f);
        ay += c0w * fmaxf(fmaf(w0.y, sc1, sh1), 0.f);
        bx += c1w * fmaxf(fmaf(w1.x, sc0, sh0), 0.f);
        by += c1w * fmaxf(fmaf(w1.y, sc1, sh1), 0.f);
        ax += c2w * fmaxf(fmaf(w2.x, sc0, sh0), 0.f);
        ay += c2w * fmaxf(fmaf(w2.y, sc1, sh1), 0.f);
        bx += c3w * fmaxf(fmaf(w3.x, sc0, sh0), 0.f);
        by += c3w * fmaxf(fmaf(w3.y, sc1, sh1), 0.f);
    }
    for (; p < e; p++) {
        int j = g_col[p];
        float cw = g_cw[p];
        float2 w = __half22float2(hh[j * 32 + lane]);
        ax += cw * fmaxf(fmaf(w.x, sc0, sh0), 0.f);
        ay += cw * fmaxf(fmaf(w.y, sc1, sh1), 0.f);
    }
    ((float2*)out)[node * 32 + lane] = make_float2(ax + bx, ay + by);
}

// D=16 over raw x with fused input-BN affine. 4 nodes/warp, 8 lanes/node.
__global__ void k_agg16p(const float* __restrict__ x, const float* __restrict__ bng,
                         const float* __restrict__ bnb, float* __restrict__ out) {
    int t = blockIdx.x * blockDim.x + threadIdx.x;
    int warp = t >> 5, lane = t & 31;
    int node = warp * 4 + (lane >> 3);
    int fl = lane & 7;
    if (node >= NN) return;
    const float invn = 1.0f / NN;
    int c0 = 2 * fl, c1 = 2 * fl + 1;
    float m0 = g_stats_in[c0] * invn, m1 = g_stats_in[c1] * invn;
    float v0 = g_stats_in[IND + c0] * invn - m0 * m0;
    float v1 = g_stats_in[IND + c1] * invn - m1 * m1;
    float sc0 = bng[c0] * rsqrtf(v0 + BN_EPS), sc1 = bng[c1] * rsqrtf(v1 + BN_EPS);
    float sh0 = bnb[c0] - m0 * sc0, sh1 = bnb[c1] - m1 * sc1;

    const float2* __restrict__ h2 = (const float2*)x;
    float di = g_dis[node];
    float2 hv = h2[node * 8 + fl];
    float ax = di * di * fmaf(hv.x, sc0, sh0);
    float ay = di * di * fmaf(hv.y, sc1, sh1);
    float bx = 0.f, by = 0.f;
    int s = g_rowptr[node], e = g_rowptr[node + 1];
    int p = s;
    for (; p + 4 <= e; p += 4) {
        int j0 = g_col[p], j1 = g_col[p + 1], j2 = g_col[p + 2], j3 = g_col[p + 3];
        float c0w = g_cw[p], c1w = g_cw[p + 1], c2w = g_cw[p + 2], c3w = g_cw[p + 3];
        float2 w0 = h2[j0 * 8 + fl];
        float2 w1 = h2[j1 * 8 + fl];
        float2 w2 = h2[j2 * 8 + fl];
        float2 w3 = h2[j3 * 8 + fl];
        ax += c0w * fmaf(w0.x, sc0, sh0);
        ay += c0w * fmaf(w0.y, sc1, sh1);
        bx += c1w * fmaf(w1.x, sc0, sh0);
        by += c1w * fmaf(w1.y, sc1, sh1);
        ax += c2w * fmaf(w2.x, sc0, sh0);
        ay += c2w * fmaf(w2.y, sc1, sh1);
        bx += c3w * fmaf(w3.x, sc0, sh0);
        by += c3w * fmaf(w3.y, sc1, sh1);
    }
    for (; p < e; p++) {
        int j = g_col[p];
        float cw = g_cw[p];
        float2 w = h2[j * 8 + fl];
        ax += cw * fmaf(w.x, sc0, sh0);
        ay += cw * fmaf(w.y, sc1, sh1);
    }
    ((float2*)out)[node * 8 + fl] = make_float2(ax + bx, ay + by);
}

// ---------------- dense matmul (f32x2 packed FMA, half2 output) -------------
template <int CI>
__global__ void k_mm(const float* __restrict__ A, const float* __restrict__ W,
                     const float* __restrict__ b, __half* __restrict__ outh) {
    __shared__ __align__(16) float sW[CI * HD];
    __shared__ __align__(16) float sB[HD];
    for (int t = threadIdx.x; t < CI * HD; t += blockDim.x) sW[t] = W[t];
    for (int t = threadIdx.x; t < HD; t += blockDim.x) sB[t] = b[t];
    __syncthreads();
    int row = blockIdx.x * blockDim.x + threadIdx.x;
    if (row >= NN) return;
    unsigned long long acc[HD / 2];
    #pragma unroll
    for (int c = 0; c < HD / 2; c++)
        acc[c] = *(const unsigned long long*)&sB[2 * c];
    const float4* A4 = (const float4*)(A + row * CI);
    #pragma unroll
    for (int k0 = 0; k0 < CI; k0 += 4) {
        float4 a4 = A4[k0 / 4];
        float av[4] = {a4.x, a4.y, a4.z, a4.w};
        #pragma unroll
        for (int kk = 0; kk < 4; kk++) {
            unsigned long long xx = pack2(av[kk], av[kk]);
            const unsigned long long* wr =
                (const unsigned long long*)&sW[(k0 + kk) * HD];
            #pragma unroll
            for (int c = 0; c < HD / 2; c++) fma2(acc[c], xx, wr[c]);
        }
    }
    unsigned long long* o8 = (unsigned long long*)(outh + row * HD);
    #pragma unroll
    for (int c = 0; c < HD / 4; c++) {
        unsigned u0 = h2u(lo32(acc[2 * c]), hi32(acc[2 * c]));
        unsigned u1 = h2u(lo32(acc[2 * c + 1]), hi32(acc[2 * c + 1]));
        o8[c] = ((unsigned long long)u1 << 32) | u0;
    }
}

// ---------------- global mean pool (half2 input, fused BN+ReLU) -------------
__global__ void k_pool(const __half2* __restrict__ hh, const float* __restrict__ stats,
                       const float* __restrict__ g, const float* __restrict__ be,
                       const int* __restrict__ bid) {
    int t = blockIdx.x * blockDim.x + threadIdx.x;
    int w = t >> 5, lane = t & 31;
    int base = w * 8;
    if (base >= NN) return;
    const float invn = 1.0f / NN;
    int c0 = 2 * lane, c1 = 2 * lane + 1;
    float m0 = stats[c0] * invn, m1 = stats[c1] * invn;
    float v0 = stats[HD + c0] * invn - m0 * m0;
    float v1 = stats[HD + c1] * invn - m1 * m1;
    float sc0 = g[c0] * rsqrtf(v0 + BN_EPS), sc1 = g[c1] * rsqrtf(v1 + BN_EPS);
    float sh0 = be[c0] - m0 * sc0, sh1 = be[c1] - m1 * sc1;

    float2 acc = make_float2(0.f, 0.f);
    int cur = -1, cnt = 0;
    for (int k = 0; k < 8; k++) {
        int i = base + k;
        if (i >= NN) break;
        int gr = bid[i];
        if (gr != cur) {
            if (cur >= 0) {
                atomicAdd(&g_pool[cur * HD + c0], acc.x);
                atomicAdd(&g_pool[cur * HD + c1], acc.y);
                if (lane == 0) atomicAdd(&g_pcnt[cur], cnt);
            }
            cur = gr; acc = make_float2(0.f, 0.f); cnt = 0;
        }
        float2 v = __half22float2(hh[i * 32 + lane]);
        acc.x += fmaxf(fmaf(v.x, sc0, sh0), 0.f);
        acc.y += fmaxf(fmaf(v.y, sc1, sh1), 0.f);
        cnt++;
    }
    if (cur >= 0) {
        atomicAdd(&g_pool[cur * HD + c0], acc.x);
        atomicAdd(&g_pool[cur * HD + c1], acc.y);
        if (lane == 0) atomicAdd(&g_pcnt[cur], cnt);
    }
}

// ---------------- classifier head ------------------------------------------
__global__ void k_head(const float* __restrict__ Wc1, const float* __restrict__ bc1,
                       const float* __restrict__ Wc2, const float* __restrict__ bc2,
                       float* __restrict__ out) {
    __shared__ float sW[HD * HD];
    __shared__ float sb1[HD];
    __shared__ float sW2[HD * 2];
    __shared__ float sb2[2];
    for (int t = threadIdx.x; t < HD * HD; t += blockDim.x) sW[t] = Wc1[t];
    for (int t = threadIdx.x; t < HD; t += blockDim.x) sb1[t] = bc1[t];
    for (int t = threadIdx.x; t < HD * 2; t += blockDim.x) sW2[t] = Wc2[t];
    if (threadIdx.x < 2) sb2[threadIdx.x] = bc2[threadIdx.x];
    __syncthreads();
    int g = blockIdx.x * blockDim.x + threadIdx.x;
    if (g >= GG) return;
    float cnt = fmaxf((float)g_pcnt[g], 1.0f);
    float inv = 1.0f / cnt;
    float p[HD];
    #pragma unroll
    for (int f = 0; f < HD; f++) p[f] = g_pool[g * HD + f] * inv;
    float o0 = sb2[0], o1 = sb2[1];
    #pragma unroll 8
    for (int c = 0; c < HD; c++) {
        float z = sb1[c];
        #pragma unroll
        for (int k = 0; k < HD; k++) z += p[k] * sW[k * HD + c];
        z = fmaxf(z, 0.f);
        o0 += z * sW2[c * 2];
        o1 += z * sW2[c * 2 + 1];
    }
    out[g * 2] = o0;
    out[g * 2 + 1] = o1;
}

// ---------------- launch ----------------------------------------------------
extern "C" void kernel_launch(void* const* d_in, const int* in_sizes, int n_in,
                              void* d_out, int out_size) {
    const float *x, *bng, *bnb, *W0, *b0, *g0, *be0, *W1, *b1, *g1, *be1;
    const float *W2, *b2, *g2, *be2, *Wc1, *bc1, *Wc2, *bc2;
    const int *ei, *bid;

    if (in_sizes[1] == 2 * EE) {
        x   = (const float*)d_in[0];  ei  = (const int*)d_in[1];  bid = (const int*)d_in[2];
        bng = (const float*)d_in[3];  bnb = (const float*)d_in[4];
        W0  = (const float*)d_in[5];  b0  = (const float*)d_in[6];
        g0  = (const float*)d_in[7];  be0 = (const float*)d_in[8];
        W1  = (const float*)d_in[9];  b1  = (const float*)d_in[10];
        g1  = (const float*)d_in[11]; be1 = (const float*)d_in[12];
        W2  = (const float*)d_in[13]; b2  = (const float*)d_in[14];
        g2  = (const float*)d_in[15]; be2 = (const float*)d_in[16];
        Wc1 = (const float*)d_in[17]; bc1 = (const float*)d_in[18];
        Wc2 = (const float*)d_in[19]; bc2 = (const float*)d_in[20];
    } else {
        x   = (const float*)d_in[0];
        bng = (const float*)d_in[1];  bnb = (const float*)d_in[2];
        W0  = (const float*)d_in[3];  b0  = (const float*)d_in[4];
        g0  = (const float*)d_in[5];  be0 = (const float*)d_in[6];
        W1  = (const float*)d_in[7];  b1  = (const float*)d_in[8];
        g1  = (const float*)d_in[9];  be1 = (const float*)d_in[10];
        W2  = (const float*)d_in[11]; b2  = (const float*)d_in[12];
        g2  = (const float*)d_in[13]; be2 = (const float*)d_in[14];
        Wc1 = (const float*)d_in[15]; bc1 = (const float*)d_in[16];
        Wc2 = (const float*)d_in[17]; bc2 = (const float*)d_in[18];
        ei  = (const int*)d_in[19];   bid = (const int*)d_in[20];
    }

    float *a16, *Dbuf, *st;
    __half *H;
    cudaGetSymbolAddress((void**)&a16, g_agg16);
    cudaGetSymbolAddress((void**)&Dbuf, g_D);
    cudaGetSymbolAddress((void**)&H, g_H);
    cudaGetSymbolAddress((void**)&st, g_stats);
    __half *H0 = H, *H1 = H + NN * HD;
    float *S1 = st, *S2 = st + 128, *S3 = st + 256;
    float* out = (float*)d_out;

    const int nb_scan1 = (NN + 511) / 512;
    const int nb_n = (NN + 255) / 256;
    const int nb_edge = (EE / 4 + 255) / 256;
    const int nb_agg64 = (NN * 32 + 255) / 256;
    const int nb_agg16 = (((NN + 3) / 4) * 32 + 255) / 256;
    const int nb_mm = (NN + 127) / 128;
    const int nb_pool = (((NN + 7) / 8) * 32 + 255) / 256;

    // ---- graph build + input stats ----
    k_init<<<256, 256>>>();                               // 0
    k_deg<<<nb_edge, 256>>>(ei);                          // 1
    k_scan1<<<nb_scan1, 512>>>();                         // 2  (also computes dis)
    k_stats_in<<<256, 256>>>(x);                          // 3  <- ncu capture
    k_scan2<<<1, 256>>>(nb_scan1);                        // 4
    k_scan3<<<nb_n, 256>>>();                             // 5
    k_fill<<<nb_edge, 256>>>(ei);                         // 6

    // ---- layer 0 (16 -> 64): agg over BN(x), mm -> H0, stats ----
    k_agg16p<<<nb_agg16, 256>>>(x, bng, bnb, a16);        // 7
    k_mm<IND><<<nb_mm, 128>>>(a16, W0, b0, H0);           // 8
    k_cstats<<<256, 256>>>((const __half2*)H0, S1);       // 9

    // ---- layer 1 (64 -> 64): gather fp16, agg fp32, mm -> H1 ----
    k_agg64<<<nb_agg64, 256>>>((const __half2*)H0, S1, g0, be0, Dbuf); // 10
    k_mm<HD><<<nb_mm, 128>>>(Dbuf, W1, b1, H1);                        // 11
    k_cstats<<<256, 256>>>((const __half2*)H1, S2);                    // 12

    // ---- layer 2 (64 -> 64) ----
    k_agg64<<<nb_agg64, 256>>>((const __half2*)H1, S2, g1, be1, Dbuf); // 13
    k_mm<HD><<<nb_mm, 128>>>(Dbuf, W2, b2, H0);                        // 14
    k_cstats<<<256, 256>>>((const __half2*)H0, S3);                    // 15

    // ---- pool (applies BN2+relu) + head ----
    k_pool<<<nb_pool, 256>>>((const __half2*)H0, S3, g2, be2, bid);    // 16
    k_head<<<(GG + 63) / 64, 64>>>(Wc1, bc1, Wc2, bc2, out);           // 17
}

// round 10
// speedup vs baseline: 1.2621x; 1.0211x over previous
#include <cuda_runtime.h>
#include <cuda_fp16.h>

#define NN 100000
#define EE 1200000
#define GG 512
#define IND 16
#define HD 64
#define BN_EPS 1e-5f
#define CSRCAP (EE + 3 * NN + 16)

// ---------------- scratch (static device globals; no allocation) ------------
__device__ int   g_deg[NN];
__device__ int   g_cursor[NN];
__device__ float g_dis[NN];
__device__ int   g_rowptr[NN + 1];
__device__ __align__(16) int2 g_ecw[CSRCAP];   // interleaved (col, cw bits)
__device__ int   g_bsums[256];
__device__ int   g_boffs[256];
__device__ __align__(16) float  g_agg16[NN * IND];
__device__ __align__(16) float  g_D[NN * HD];          // fp32 agg64 output
__device__ __align__(16) __half g_H[2][NN * HD];       // fp16 layer outputs
__device__ float g_stats[4 * 128];   // 3 used: [64 sums][64 sumsq] each
__device__ float g_stats_in[2 * IND];
__device__ float g_pool[GG * HD];
__device__ int   g_pcnt[GG];

// ---------------- f32x2 / half helpers ---------------------------------------
__device__ __forceinline__ unsigned long long pack2(float lo, float hi) {
    unsigned long long r;
    asm("mov.b64 %0, {%1, %2};" : "=l"(r) : "f"(lo), "f"(hi));
    return r;
}
__device__ __forceinline__ void fma2(unsigned long long& d, unsigned long long a,
                                     unsigned long long b) {
    asm("fma.rn.f32x2 %0, %1, %2, %0;" : "+l"(d) : "l"(a), "l"(b));
}
__device__ __forceinline__ float lo32(unsigned long long v) {
    return __uint_as_float((unsigned)v);
}
__device__ __forceinline__ float hi32(unsigned long long v) {
    return __uint_as_float((unsigned)(v >> 32));
}
__device__ __forceinline__ unsigned h2u(float lo, float hi) {
    __half2 h = __floats2half2_rn(lo, hi);
    return *(unsigned*)&h;
}

// ---------------- init ------------------------------------------------------
__global__ void k_init() {
    int t0 = blockIdx.x * blockDim.x + threadIdx.x;
    int stride = gridDim.x * blockDim.x;
    for (int i = t0; i < NN; i += stride) { g_deg[i] = 1; g_cursor[i] = 0; }
    for (int i = t0; i < 4 * 128; i += stride) g_stats[i] = 0.f;
    for (int i = t0; i < 2 * IND; i += stride) g_stats_in[i] = 0.f;
    for (int i = t0; i < GG * HD; i += stride) g_pool[i] = 0.f;
    for (int i = t0; i < GG; i += stride) g_pcnt[i] = 0;
}

// ---------------- degree (int4 edge reads) ----------------------------------
__global__ void k_deg(const int* __restrict__ ei) {
    const int4* d4 = (const int4*)(ei + EE);
    int t0 = blockIdx.x * blockDim.x + threadIdx.x;
    int stride = gridDim.x * blockDim.x;
    for (int e = t0; e < EE / 4; e += stride) {
        int4 v = d4[e];
        atomicAdd(&g_deg[v.x], 1);
        atomicAdd(&g_deg[v.y], 1);
        atomicAdd(&g_deg[v.z], 1);
        atomicAdd(&g_deg[v.w], 1);
    }
}

// ---------------- scan of PADDED counts (3-phase), fused dis -----------------
// padded count per row = ((deg-1)+3) & ~3  -> every CSR row 4-aligned.
__global__ void k_scan1() {
    __shared__ int sm[512];
    int tid = threadIdx.x;
    int i = blockIdx.x * 512 + tid;
    int v = 0;
    if (i < NN) {
        int deg = g_deg[i];
        g_dis[i] = rsqrtf((float)deg);
        v = ((deg - 1) + 3) & ~3;
    }
    sm[tid] = v;
    __syncthreads();
    #pragma unroll
    for (int off = 1; off < 512; off <<= 1) {
        int t = (tid >= off) ? sm[tid - off] : 0;
        __syncthreads();
        sm[tid] += t;
        __syncthreads();
    }
    if (i < NN) g_rowptr[i] = sm[tid] - v;      // local exclusive
    if (tid == 511) g_bsums[blockIdx.x] = sm[511];
}

__global__ void k_scan2(int nb) {
    __shared__ int sm[256];
    int tid = threadIdx.x;
    int v = (tid < nb) ? g_bsums[tid] : 0;
    sm[tid] = v;
    __syncthreads();
    #pragma unroll
    for (int off = 1; off < 256; off <<= 1) {
        int t = (tid >= off) ? sm[tid - off] : 0;
        __syncthreads();
        sm[tid] += t;
        __syncthreads();
    }
    g_boffs[tid] = sm[tid] - v;                 // exclusive block offsets
    if (tid == nb - 1) g_rowptr[NN] = sm[tid];  // total padded count
}

__global__ void k_scan3() {
    int i = blockIdx.x * blockDim.x + threadIdx.x;
    if (i < NN) g_rowptr[i] += g_boffs[i >> 9];
}

// ---------------- zero ONLY the pad slots (<=3 per row) ----------------------
// pad slots = [rowptr[i] + (deg[i]-1), rowptr[i+1]). col=0 & cw=0 is harmless.
__global__ void k_pad() {
    int i = blockIdx.x * blockDim.x + threadIdx.x;
    if (i >= NN) return;
    int e0 = g_rowptr[i] + (g_deg[i] - 1);
    int e1 = g_rowptr[i + 1];
    for (int p = e0; p < e1; p++) g_ecw[p] = make_int2(0, 0);
}

// ---------------- CSR fill (int4 edge reads; int2 interleaved out) ----------
__global__ void k_fill(const int* __restrict__ ei) {
    const int4* s4 = (const int4*)ei;
    const int4* d4 = (const int4*)(ei + EE);
    int t0 = blockIdx.x * blockDim.x + threadIdx.x;
    int stride = gridDim.x * blockDim.x;
    for (int e = t0; e < EE / 4; e += stride) {
        int4 s = s4[e];
        int4 d = d4[e];
        int p;
        p = g_rowptr[d.x] + atomicAdd(&g_cursor[d.x], 1);
        g_ecw[p] = make_int2(s.x, __float_as_int(g_dis[s.x] * g_dis[d.x]));
        p = g_rowptr[d.y] + atomicAdd(&g_cursor[d.y], 1);
        g_ecw[p] = make_int2(s.y, __float_as_int(g_dis[s.y] * g_dis[d.y]));
        p = g_rowptr[d.z] + atomicAdd(&g_cursor[d.z], 1);
        g_ecw[p] = make_int2(s.z, __float_as_int(g_dis[s.z] * g_dis[d.z]));
        p = g_rowptr[d.w] + atomicAdd(&g_cursor[d.w], 1);
        g_ecw[p] = make_int2(s.w, __float_as_int(g_dis[s.w] * g_dis[d.w]));
    }
}

// ---------------- input BN stats (D=16 over raw x) --------------------------
__global__ void k_stats_in(const float* __restrict__ src) {
    __shared__ float ss[2 * IND];
    for (int t = threadIdx.x; t < 2 * IND; t += blockDim.x) ss[t] = 0.f;
    __syncthreads();
    float ls[IND], lq[IND];
    #pragma unroll
    for (int c = 0; c < IND; c++) { ls[c] = 0.f; lq[c] = 0.f; }
    int stride = gridDim.x * blockDim.x;
    for (int r = blockIdx.x * blockDim.x + threadIdx.x; r < NN; r += stride) {
        const float4* row = (const float4*)(src + r * IND);
        #pragma unroll
        for (int q = 0; q < IND / 4; q++) {
            float4 v = row[q];
            ls[4*q+0] += v.x; lq[4*q+0] += v.x * v.x;
            ls[4*q+1] += v.y; lq[4*q+1] += v.y * v.y;
            ls[4*q+2] += v.z; lq[4*q+2] += v.z * v.z;
            ls[4*q+3] += v.w; lq[4*q+3] += v.w * v.w;
        }
    }
    #pragma unroll
    for (int c = 0; c < IND; c++) {
        #pragma unroll
        for (int o = 16; o > 0; o >>= 1) {
            ls[c] += __shfl_xor_sync(0xffffffffu, ls[c], o);
            lq[c] += __shfl_xor_sync(0xffffffffu, lq[c], o);
        }
    }
    if ((threadIdx.x & 31) == 0) {
        #pragma unroll
        for (int c = 0; c < IND; c++) {
            atomicAdd(&ss[c], ls[c]);
            atomicAdd(&ss[IND + c], lq[c]);
        }
    }
    __syncthreads();
    for (int t = threadIdx.x; t < 2 * IND; t += blockDim.x) atomicAdd(&g_stats_in[t], ss[t]);
}

// ---------------- column stats over D=64 (half2 input) ----------------------
__global__ void k_cstats(const __half2* __restrict__ src, float* __restrict__ stats) {
    __shared__ float ss[2 * HD];
    for (int t = threadIdx.x; t < 2 * HD; t += blockDim.x) ss[t] = 0.f;
    __syncthreads();
    int c2 = threadIdx.x & 31;                 // column pair
    int rpi = (blockDim.x / 32) * gridDim.x;   // rows per iteration
    int r0 = blockIdx.x * (blockDim.x / 32) + (threadIdx.x >> 5);
    float ls0 = 0.f, lq0 = 0.f, ls1 = 0.f, lq1 = 0.f;
    for (int r = r0; r < NN; r += rpi) {
        float2 v = __half22float2(src[r * 32 + c2]);
        ls0 += v.x; lq0 += v.x * v.x;
        ls1 += v.y; lq1 += v.y * v.y;
    }
    atomicAdd(&ss[2 * c2], ls0);
    atomicAdd(&ss[2 * c2 + 1], ls1);
    atomicAdd(&ss[HD + 2 * c2], lq0);
    atomicAdd(&ss[HD + 2 * c2 + 1], lq1);
    __syncthreads();
    for (int t = threadIdx.x; t < 2 * HD; t += blockDim.x) atomicAdd(&stats[t], ss[t]);
}

// ---------------- aggregation: gather half2, fused BN+ReLU, fp32 math -------
// D=64: one warp per node, lane owns column pair. Padded rows: metadata for
// 4 edges = two int4 loads (vs 8 scalar LDGs).
__global__ void k_agg64(const __half2* __restrict__ hh, const float* __restrict__ stats,
                        const float* __restrict__ g, const float* __restrict__ be,
                        float* __restrict__ out) {
    int t = blockIdx.x * blockDim.x + threadIdx.x;
    int node = t >> 5, lane = t & 31;
    if (node >= NN) return;
    const float invn = 1.0f / NN;
    int c0 = 2 * lane, c1 = 2 * lane + 1;
    float m0 = stats[c0] * invn, m1 = stats[c1] * invn;
    float v0 = stats[HD + c0] * invn - m0 * m0;
    float v1 = stats[HD + c1] * invn - m1 * m1;
    float sc0 = g[c0] * rsqrtf(v0 + BN_EPS), sc1 = g[c1] * rsqrtf(v1 + BN_EPS);
    float sh0 = be[c0] - m0 * sc0, sh1 = be[c1] - m1 * sc1;

    float di = g_dis[node];
    float2 hv = __half22float2(hh[node * 32 + lane]);
    float ax = di * di * fmaxf(fmaf(hv.x, sc0, sh0), 0.f);
    float ay = di * di * fmaxf(fmaf(hv.y, sc1, sh1), 0.f);
    float bx = 0.f, by = 0.f;
    int s = g_rowptr[node], e = g_rowptr[node + 1];     // multiples of 4
    for (int p = s; p < e; p += 4) {
        int4 ea = *(const int4*)&g_ecw[p];       // edges p, p+1
        int4 eb = *(const int4*)&g_ecw[p + 2];   // edges p+2, p+3
        float c0w = __int_as_float(ea.y), c1w = __int_as_float(ea.w);
        float c2w = __int_as_float(eb.y), c3w = __int_as_float(eb.w);
        float2 w0 = __half22float2(hh[ea.x * 32 + lane]);
        float2 w1 = __half22float2(hh[ea.z * 32 + lane]);
        float2 w2 = __half22float2(hh[eb.x * 32 + lane]);
        float2 w3 = __half22float2(hh[eb.z * 32 + lane]);
        ax += c0w * fmaxf(fmaf(w0.x, sc0, sh0), 0.f);
        ay += c0w * fmaxf(fmaf(w0.y, sc1, sh1), 0.f);
        bx += c1w * fmaxf(fmaf(w1.x, sc0, sh0), 0.f);
        by += c1w * fmaxf(fmaf(w1.y, sc1, sh1), 0.f);
        ax += c2w * fmaxf(fmaf(w2.x, sc0, sh0), 0.f);
        ay += c2w * fmaxf(fmaf(w2.y, sc1, sh1), 0.f);
        bx += c3w * fmaxf(fmaf(w3.x, sc0, sh0), 0.f);
        by += c3w * fmaxf(fmaf(w3.y, sc1, sh1), 0.f);
    }
    ((float2*)out)[node * 32 + lane] = make_float2(ax + bx, ay + by);
}

// D=16 over raw x with fused input-BN affine. 4 nodes/warp, 8 lanes/node.
__global__ void k_agg16p(const float* __restrict__ x, const float* __restrict__ bng,
                         const float* __restrict__ bnb, float* __restrict__ out) {
    int t = blockIdx.x * blockDim.x + threadIdx.x;
    int warp = t >> 5, lane = t & 31;
    int node = warp * 4 + (lane >> 3);
    int fl = lane & 7;
    if (node >= NN) return;
    const float invn = 1.0f / NN;
    int c0 = 2 * fl, c1 = 2 * fl + 1;
    float m0 = g_stats_in[c0] * invn, m1 = g_stats_in[c1] * invn;
    float v0 = g_stats_in[IND + c0] * invn - m0 * m0;
    float v1 = g_stats_in[IND + c1] * invn - m1 * m1;
    float sc0 = bng[c0] * rsqrtf(v0 + BN_EPS), sc1 = bng[c1] * rsqrtf(v1 + BN_EPS);
    float sh0 = bnb[c0] - m0 * sc0, sh1 = bnb[c1] - m1 * sc1;

    const float2* __restrict__ h2 = (const float2*)x;
    float di = g_dis[node];
    float2 hv = h2[node * 8 + fl];
    float ax = di * di * fmaf(hv.x, sc0, sh0);
    float ay = di * di * fmaf(hv.y, sc1, sh1);
    float bx = 0.f, by = 0.f;
    int s = g_rowptr[node], e = g_rowptr[node + 1];
    for (int p = s; p < e; p += 4) {
        int4 ea = *(const int4*)&g_ecw[p];
        int4 eb = *(const int4*)&g_ecw[p + 2];
        float c0w = __int_as_float(ea.y), c1w = __int_as_float(ea.w);
        float c2w = __int_as_float(eb.y), c3w = __int_as_float(eb.w);
        float2 w0 = h2[ea.x * 8 + fl];
        float2 w1 = h2[ea.z * 8 + fl];
        float2 w2 = h2[eb.x * 8 + fl];
        float2 w3 = h2[eb.z * 8 + fl];
        ax += c0w * fmaf(w0.x, sc0, sh0);
        ay += c0w * fmaf(w0.y, sc1, sh1);
        bx += c1w * fmaf(w1.x, sc0, sh0);
        by += c1w * fmaf(w1.y, sc1, sh1);
        ax += c2w * fmaf(w2.x, sc0, sh0);
        ay += c2w * fmaf(w2.y, sc1, sh1);
        bx += c3w * fmaf(w3.x, sc0, sh0);
        by += c3w * fmaf(w3.y, sc1, sh1);
    }
    ((float2*)out)[node * 8 + fl] = make_float2(ax + bx, ay + by);
}

// ---------------- dense matmul (f32x2 packed FMA, half2 output) -------------
template <int CI>
__global__ void k_mm(const float* __restrict__ A, const float* __restrict__ W,
                     const float* __restrict__ b, __half* __restrict__ outh) {
    __shared__ __align__(16) float sW[CI * HD];
    __shared__ __align__(16) float sB[HD];
    for (int t = threadIdx.x; t < CI * HD; t += blockDim.x) sW[t] = W[t];
    for (int t = threadIdx.x; t < HD; t += blockDim.x) sB[t] = b[t];
    __syncthreads();
    int row = blockIdx.x * blockDim.x + threadIdx.x;
    if (row >= NN) return;
    unsigned long long acc[HD / 2];
    #pragma unroll
    for (int c = 0; c < HD / 2; c++)
        acc[c] = *(const unsigned long long*)&sB[2 * c];
    const float4* A4 = (const float4*)(A + row * CI);
    #pragma unroll
    for (int k0 = 0; k0 < CI; k0 += 4) {
        float4 a4 = A4[k0 / 4];
        float av[4] = {a4.x, a4.y, a4.z, a4.w};
        #pragma unroll
        for (int kk = 0; kk < 4; kk++) {
            unsigned long long xx = pack2(av[kk], av[kk]);
            const unsigned long long* wr =
                (const unsigned long long*)&sW[(k0 + kk) * HD];
            #pragma unroll
            for (int c = 0; c < HD / 2; c++) fma2(acc[c], xx, wr[c]);
        }
    }
    unsigned long long* o8 = (unsigned long long*)(outh + row * HD);
    #pragma unroll
    for (int c = 0; c < HD / 4; c++) {
        unsigned u0 = h2u(lo32(acc[2 * c]), hi32(acc[2 * c]));
        unsigned u1 = h2u(lo32(acc[2 * c + 1]), hi32(acc[2 * c + 1]));
        o8[c] = ((unsigned long long)u1 << 32) | u0;
    }
}

// ---------------- global mean pool (half2 input, fused BN+ReLU) -------------
__global__ void k_pool(const __half2* __restrict__ hh, const float* __restrict__ stats,
                       const float* __restrict__ g, const float* __restrict__ be,
                       const int* __restrict__ bid) {
    int t = blockIdx.x * blockDim.x + threadIdx.x;
    int w = t >> 5, lane = t & 31;
    int base = w * 8;
    if (base >= NN) return;
    const float invn = 1.0f / NN;
    int c0 = 2 * lane, c1 = 2 * lane + 1;
    float m0 = stats[c0] * invn, m1 = stats[c1] * invn;
    float v0 = stats[HD + c0] * invn - m0 * m0;
    float v1 = stats[HD + c1] * invn - m1 * m1;
    float sc0 = g[c0] * rsqrtf(v0 + BN_EPS), sc1 = g[c1] * rsqrtf(v1 + BN_EPS);
    float sh0 = be[c0] - m0 * sc0, sh1 = be[c1] - m1 * sc1;

    float2 acc = make_float2(0.f, 0.f);
    int cur = -1, cnt = 0;
    for (int k = 0; k < 8; k++) {
        int i = base + k;
        if (i >= NN) break;
        int gr = bid[i];
        if (gr != cur) {
            if (cur >= 0) {
                atomicAdd(&g_pool[cur * HD + c0], acc.x);
                atomicAdd(&g_pool[cur * HD + c1], acc.y);
                if (lane == 0) atomicAdd(&g_pcnt[cur], cnt);
            }
            cur = gr; acc = make_float2(0.f, 0.f); cnt = 0;
        }
        float2 v = __half22float2(hh[i * 32 + lane]);
        acc.x += fmaxf(fmaf(v.x, sc0, sh0), 0.f);
        acc.y += fmaxf(fmaf(v.y, sc1, sh1), 0.f);
        cnt++;
    }
    if (cur >= 0) {
        atomicAdd(&g_pool[cur * HD + c0], acc.x);
        atomicAdd(&g_pool[cur * HD + c1], acc.y);
        if (lane == 0) atomicAdd(&g_pcnt[cur], cnt);
    }
}

// ---------------- classifier head ------------------------------------------
__global__ void k_head(const float* __restrict__ Wc1, const float* __restrict__ bc1,
                       const float* __restrict__ Wc2, const float* __restrict__ bc2,
                       float* __restrict__ out) {
    __shared__ float sW[HD * HD];
    __shared__ float sb1[HD];
    __shared__ float sW2[HD * 2];
    __shared__ float sb2[2];
    for (int t = threadIdx.x; t < HD * HD; t += blockDim.x) sW[t] = Wc1[t];
    for (int t = threadIdx.x; t < HD; t += blockDim.x) sb1[t] = bc1[t];
    for (int t = threadIdx.x; t < HD * 2; t += blockDim.x) sW2[t] = Wc2[t];
    if (threadIdx.x < 2) sb2[threadIdx.x] = bc2[threadIdx.x];
    __syncthreads();
    int g = blockIdx.x * blockDim.x + threadIdx.x;
    if (g >= GG) return;
    float cnt = fmaxf((float)g_pcnt[g], 1.0f);
    float inv = 1.0f / cnt;
    float p[HD];
    #pragma unroll
    for (int f = 0; f < HD; f++) p[f] = g_pool[g * HD + f] * inv;
    float o0 = sb2[0], o1 = sb2[1];
    #pragma unroll 8
    for (int c = 0; c < HD; c++) {
        float z = sb1[c];
        #pragma unroll
        for (int k = 0; k < HD; k++) z += p[k] * sW[k * HD + c];
        z = fmaxf(z, 0.f);
        o0 += z * sW2[c * 2];
        o1 += z * sW2[c * 2 + 1];
    }
    out[g * 2] = o0;
    out[g * 2 + 1] = o1;
}

// ---------------- launch ----------------------------------------------------
extern "C" void kernel_launch(void* const* d_in, const int* in_sizes, int n_in,
                              void* d_out, int out_size) {
    const float *x, *bng, *bnb, *W0, *b0, *g0, *be0, *W1, *b1, *g1, *be1;
    const float *W2, *b2, *g2, *be2, *Wc1, *bc1, *Wc2, *bc2;
    const int *ei, *bid;

    if (in_sizes[1] == 2 * EE) {
        x   = (const float*)d_in[0];  ei  = (const int*)d_in[1];  bid = (const int*)d_in[2];
        bng = (const float*)d_in[3];  bnb = (const float*)d_in[4];
        W0  = (const float*)d_in[5];  b0  = (const float*)d_in[6];
        g0  = (const float*)d_in[7];  be0 = (const float*)d_in[8];
        W1  = (const float*)d_in[9];  b1  = (const float*)d_in[10];
        g1  = (const float*)d_in[11]; be1 = (const float*)d_in[12];
        W2  = (const float*)d_in[13]; b2  = (const float*)d_in[14];
        g2  = (const float*)d_in[15]; be2 = (const float*)d_in[16];
        Wc1 = (const float*)d_in[17]; bc1 = (const float*)d_in[18];
        Wc2 = (const float*)d_in[19]; bc2 = (const float*)d_in[20];
    } else {
        x   = (const float*)d_in[0];
        bng = (const float*)d_in[1];  bnb = (const float*)d_in[2];
        W0  = (const float*)d_in[3];  b0  = (const float*)d_in[4];
        g0  = (const float*)d_in[5];  be0 = (const float*)d_in[6];
        W1  = (const float*)d_in[7];  b1  = (const float*)d_in[8];
        g1  = (const float*)d_in[9];  be1 = (const float*)d_in[10];
        W2  = (const float*)d_in[11]; b2  = (const float*)d_in[12];
        g2  = (const float*)d_in[13]; be2 = (const float*)d_in[14];
        Wc1 = (const float*)d_in[15]; bc1 = (const float*)d_in[16];
        Wc2 = (const float*)d_in[17]; bc2 = (const float*)d_in[18];
        ei  = (const int*)d_in[19];   bid = (const int*)d_in[20];
    }

    float *a16, *Dbuf, *st;
    __half *H;
    cudaGetSymbolAddress((void**)&a16, g_agg16);
    cudaGetSymbolAddress((void**)&Dbuf, g_D);
    cudaGetSymbolAddress((void**)&H, g_H);
    cudaGetSymbolAddress((void**)&st, g_stats);
    __half *H0 = H, *H1 = H + NN * HD;
    float *S1 = st, *S2 = st + 128, *S3 = st + 256;
    float* out = (float*)d_out;

    const int nb_scan1 = (NN + 511) / 512;
    const int nb_n = (NN + 255) / 256;
    const int nb_edge = (EE / 4 + 255) / 256;
    const int nb_agg64 = (NN * 32 + 255) / 256;
    const int nb_agg16 = (((NN + 3) / 4) * 32 + 255) / 256;
    const int nb_mm = (NN + 127) / 128;
    const int nb_pool = (((NN + 7) / 8) * 32 + 255) / 256;

    // ---- graph build + input stats ----
    k_init<<<256, 256>>>();                               // 0
    k_deg<<<nb_edge, 256>>>(ei);                          // 1
    k_scan1<<<nb_scan1, 512>>>();                         // 2  (also computes dis)
    k_stats_in<<<256, 256>>>(x);                          // 3  <- ncu capture
    k_scan2<<<1, 256>>>(nb_scan1);                        // 4
    k_scan3<<<nb_n, 256>>>();                             // 5
    k_pad<<<nb_n, 256>>>();                               // 6
    k_fill<<<nb_edge, 256>>>(ei);                         // 7

    // ---- layer 0 (16 -> 64): agg over BN(x), mm -> H0, stats ----
    k_agg16p<<<nb_agg16, 256>>>(x, bng, bnb, a16);        // 8
    k_mm<IND><<<nb_mm, 128>>>(a16, W0, b0, H0);           // 9
    k_cstats<<<256, 256>>>((const __half2*)H0, S1);       // 10

    // ---- layer 1 (64 -> 64): gather fp16, agg fp32, mm -> H1 ----
    k_agg64<<<nb_agg64, 256>>>((const __half2*)H0, S1, g0, be0, Dbuf); // 11
    k_mm<HD><<<nb_mm, 128>>>(Dbuf, W1, b1, H1);                        // 12
    k_cstats<<<256, 256>>>((const __half2*)H1, S2);                    // 13

    // ---- layer 2 (64 -> 64) ----
    k_agg64<<<nb_agg64, 256>>>((const __half2*)H1, S2, g1, be1, Dbuf); // 14
    k_mm<HD><<<nb_mm, 128>>>(Dbuf, W2, b2, H0);                        // 15
    k_cstats<<<256, 256>>>((const __half2*)H0, S3);                    // 16

    // ---- pool (applies BN2+relu) + head ----
    k_pool<<<nb_pool, 256>>>((const __half2*)H0, S3, g2, be2, bid);    // 17
    k_head<<<(GG + 63) / 64, 64>>>(Wc1, bc1, Wc2, bc2, out);           // 18
}

// round 12
// speedup vs baseline: 1.3315x; 1.0550x over previous
#include <cuda_runtime.h>
#include <cuda_fp16.h>

#define NN 100000
#define EE 1200000
#define GG 512
#define IND 16
#define HD 64
#define BN_EPS 1e-5f
#define CSRCAP (EE + 3 * NN + 16)

// ---------------- scratch (static device globals; no allocation) ------------
__device__ int   g_deg[NN];
__device__ float g_dis[NN];
__device__ int   g_rowptr[NN + 1];
__device__ __align__(16) int  g_eoff[EE];      // per-edge slot from k_deg
__device__ __align__(16) int2 g_ecw[CSRCAP];   // interleaved (col, cw bits)
__device__ int   g_bsums[256];
__device__ int   g_boffs[256];
__device__ __align__(16) float  g_agg16[NN * IND];
__device__ __align__(16) __half g_H[3][NN * HD];  // fp16 buffers: H0, H1, Ht
__device__ float g_stats[4 * 128];   // 3 used: [64 sums][64 sumsq] each
__device__ float g_stats_in[2 * IND];
__device__ float g_pool[GG * HD];
__device__ int   g_pcnt[GG];

// ---------------- f32x2 / half helpers ---------------------------------------
__device__ __forceinline__ unsigned long long pack2(float lo, float hi) {
    unsigned long long r;
    asm("mov.b64 %0, {%1, %2};" : "=l"(r) : "f"(lo), "f"(hi));
    return r;
}
__device__ __forceinline__ void fma2(unsigned long long& d, unsigned long long a,
                                     unsigned long long b) {
    asm("fma.rn.f32x2 %0, %1, %2, %0;" : "+l"(d) : "l"(a), "l"(b));
}
__device__ __forceinline__ float lo32(unsigned long long v) {
    return __uint_as_float((unsigned)v);
}
__device__ __forceinline__ float hi32(unsigned long long v) {
    return __uint_as_float((unsigned)(v >> 32));
}
__device__ __forceinline__ unsigned h2u(float lo, float hi) {
    __half2 h = __floats2half2_rn(lo, hi);
    return *(unsigned*)&h;
}

// ---------------- init ------------------------------------------------------
__global__ void k_init() {
    int t0 = blockIdx.x * blockDim.x + threadIdx.x;
    int stride = gridDim.x * blockDim.x;
    for (int i = t0; i < NN; i += stride) g_deg[i] = 1;
    for (int i = t0; i < 4 * 128; i += stride) g_stats[i] = 0.f;
    for (int i = t0; i < 2 * IND; i += stride) g_stats_in[i] = 0.f;
    for (int i = t0; i < GG * HD; i += stride) g_pool[i] = 0.f;
    for (int i = t0; i < GG; i += stride) g_pcnt[i] = 0;
}

// ---------------- degree (int4 edge reads; records per-edge slot) ------------
__global__ void k_deg(const int* __restrict__ ei) {
    const int4* d4 = (const int4*)(ei + EE);
    int4* o4 = (int4*)g_eoff;
    int t0 = blockIdx.x * blockDim.x + threadIdx.x;
    int stride = gridDim.x * blockDim.x;
    for (int e = t0; e < EE / 4; e += stride) {
        int4 v = d4[e];
        int4 o;
        o.x = atomicAdd(&g_deg[v.x], 1);
        o.y = atomicAdd(&g_deg[v.y], 1);
        o.z = atomicAdd(&g_deg[v.z], 1);
        o.w = atomicAdd(&g_deg[v.w], 1);
        o4[e] = o;                       // old value >= 1; slot = old - 1
    }
}

// ---------------- scan of PADDED counts (3-phase), fused dis -----------------
// padded count per row = ((deg-1)+3) & ~3  -> every CSR row 4-aligned.
__global__ void k_scan1() {
    __shared__ int sm[512];
    int tid = threadIdx.x;
    int i = blockIdx.x * 512 + tid;
    int v = 0;
    if (i < NN) {
        int deg = g_deg[i];
        g_dis[i] = rsqrtf((float)deg);
        v = ((deg - 1) + 3) & ~3;
    }
    sm[tid] = v;
    __syncthreads();
    #pragma unroll
    for (int off = 1; off < 512; off <<= 1) {
        int t = (tid >= off) ? sm[tid - off] : 0;
        __syncthreads();
        sm[tid] += t;
        __syncthreads();
    }
    if (i < NN) g_rowptr[i] = sm[tid] - v;      // local exclusive
    if (tid == 511) g_bsums[blockIdx.x] = sm[511];
}

__global__ void k_scan2(int nb) {
    __shared__ int sm[256];
    int tid = threadIdx.x;
    int v = (tid < nb) ? g_bsums[tid] : 0;
    sm[tid] = v;
    __syncthreads();
    #pragma unroll
    for (int off = 1; off < 256; off <<= 1) {
        int t = (tid >= off) ? sm[tid - off] : 0;
        __syncthreads();
        sm[tid] += t;
        __syncthreads();
    }
    g_boffs[tid] = sm[tid] - v;                 // exclusive block offsets
    if (tid == nb - 1) g_rowptr[NN] = sm[tid];  // total padded count
}

// ---------------- scan3 + pad-slot zeroing fused -----------------------------
// pad slots for row i = [rp + deg-1, rp + padcnt)  (all from row i's own data)
__global__ void k_scan3() {
    int i = blockIdx.x * blockDim.x + threadIdx.x;
    if (i >= NN) return;
    int rp = g_rowptr[i] + g_boffs[i >> 9];
    g_rowptr[i] = rp;
    int deg = g_deg[i];
    int e0 = rp + deg - 1;
    int e1 = rp + (((deg - 1) + 3) & ~3);
    for (int p = e0; p < e1; p++) g_ecw[p] = make_int2(0, 0);
}

// ---------------- CSR fill (no atomics; uses recorded slots) -----------------
__global__ void k_fill(const int* __restrict__ ei) {
    const int4* s4 = (const int4*)ei;
    const int4* d4 = (const int4*)(ei + EE);
    const int4* o4 = (const int4*)g_eoff;
    int t0 = blockIdx.x * blockDim.x + threadIdx.x;
    int stride = gridDim.x * blockDim.x;
    for (int e = t0; e < EE / 4; e += stride) {
        int4 s = s4[e];
        int4 d = d4[e];
        int4 o = o4[e];
        int p;
        p = g_rowptr[d.x] + o.x - 1;
        g_ecw[p] = make_int2(s.x, __float_as_int(g_dis[s.x] * g_dis[d.x]));
        p = g_rowptr[d.y] + o.y - 1;
        g_ecw[p] = make_int2(s.y, __float_as_int(g_dis[s.y] * g_dis[d.y]));
        p = g_rowptr[d.z] + o.z - 1;
        g_ecw[p] = make_int2(s.z, __float_as_int(g_dis[s.z] * g_dis[d.z]));
        p = g_rowptr[d.w] + o.w - 1;
        g_ecw[p] = make_int2(s.w, __float_as_int(g_dis[s.w] * g_dis[d.w]));
    }
}

// ---------------- input BN stats (D=16 over raw x) --------------------------
__global__ void k_stats_in(const float* __restrict__ src) {
    __shared__ float ss[2 * IND];
    for (int t = threadIdx.x; t < 2 * IND; t += blockDim.x) ss[t] = 0.f;
    __syncthreads();
    float ls[IND], lq[IND];
    #pragma unroll
    for (int c = 0; c < IND; c++) { ls[c] = 0.f; lq[c] = 0.f; }
    int stride = gridDim.x * blockDim.x;
    for (int r = blockIdx.x * blockDim.x + threadIdx.x; r < NN; r += stride) {
        const float4* row = (const float4*)(src + r * IND);
        #pragma unroll
        for (int q = 0; q < IND / 4; q++) {
            float4 v = row[q];
            ls[4*q+0] += v.x; lq[4*q+0] += v.x * v.x;
            ls[4*q+1] += v.y; lq[4*q+1] += v.y * v.y;
            ls[4*q+2] += v.z; lq[4*q+2] += v.z * v.z;
            ls[4*q+3] += v.w; lq[4*q+3] += v.w * v.w;
        }
    }
    #pragma unroll
    for (int c = 0; c < IND; c++) {
        #pragma unroll
        for (int o = 16; o > 0; o >>= 1) {
            ls[c] += __shfl_xor_sync(0xffffffffu, ls[c], o);
            lq[c] += __shfl_xor_sync(0xffffffffu, lq[c], o);
        }
    }
    if ((threadIdx.x & 31) == 0) {
        #pragma unroll
        for (int c = 0; c < IND; c++) {
            atomicAdd(&ss[c], ls[c]);
            atomicAdd(&ss[IND + c], lq[c]);
        }
    }
    __syncthreads();
    for (int t = threadIdx.x; t < 2 * IND; t += blockDim.x) atomicAdd(&g_stats_in[t], ss[t]);
}

// ---------------- column stats over D=64 (half2 input) ----------------------
__global__ void k_cstats(const __half2* __restrict__ src, float* __restrict__ stats) {
    __shared__ float ss[2 * HD];
    for (int t = threadIdx.x; t < 2 * HD; t += blockDim.x) ss[t] = 0.f;
    __syncthreads();
    int c2 = threadIdx.x & 31;                 // column pair
    int rpi = (blockDim.x / 32) * gridDim.x;   // rows per iteration
    int r0 = blockIdx.x * (blockDim.x / 32) + (threadIdx.x >> 5);
    float ls0 = 0.f, lq0 = 0.f, ls1 = 0.f, lq1 = 0.f;
    for (int r = r0; r < NN; r += rpi) {
        float2 v = __half22float2(src[r * 32 + c2]);
        ls0 += v.x; lq0 += v.x * v.x;
        ls1 += v.y; lq1 += v.y * v.y;
    }
    atomicAdd(&ss[2 * c2], ls0);
    atomicAdd(&ss[2 * c2 + 1], ls1);
    atomicAdd(&ss[HD + 2 * c2], lq0);
    atomicAdd(&ss[HD + 2 * c2 + 1], lq1);
    __syncthreads();
    for (int t = threadIdx.x; t < 2 * HD; t += blockDim.x) atomicAdd(&stats[t], ss[t]);
}

// ---------------- aggregation: gather half2, fused BN+ReLU, half2 out -------
// D=64: one warp per node, lane owns column pair. fp32 accumulation.
__global__ void k_agg64(const __half2* __restrict__ hh, const float* __restrict__ stats,
                        const float* __restrict__ g, const float* __restrict__ be,
                        __half2* __restrict__ out) {
    int t = blockIdx.x * blockDim.x + threadIdx.x;
    int node = t >> 5, lane = t & 31;
    if (node >= NN) return;
    const float invn = 1.0f / NN;
    int c0 = 2 * lane, c1 = 2 * lane + 1;
    float m0 = stats[c0] * invn, m1 = stats[c1] * invn;
    float v0 = stats[HD + c0] * invn - m0 * m0;
    float v1 = stats[HD + c1] * invn - m1 * m1;
    float sc0 = g[c0] * rsqrtf(v0 + BN_EPS), sc1 = g[c1] * rsqrtf(v1 + BN_EPS);
    float sh0 = be[c0] - m0 * sc0, sh1 = be[c1] - m1 * sc1;

    float di = g_dis[node];
    float2 hv = __half22float2(hh[node * 32 + lane]);
    float ax = di * di * fmaxf(fmaf(hv.x, sc0, sh0), 0.f);
    float ay = di * di * fmaxf(fmaf(hv.y, sc1, sh1), 0.f);
    float bx = 0.f, by = 0.f;
    int s = g_rowptr[node], e = g_rowptr[node + 1];     // multiples of 4
    for (int p = s; p < e; p += 4) {
        int4 ea = *(const int4*)&g_ecw[p];       // edges p, p+1
        int4 eb = *(const int4*)&g_ecw[p + 2];   // edges p+2, p+3
        float c0w = __int_as_float(ea.y), c1w = __int_as_float(ea.w);
        float c2w = __int_as_float(eb.y), c3w = __int_as_float(eb.w);
        float2 w0 = __half22float2(hh[ea.x * 32 + lane]);
        float2 w1 = __half22float2(hh[ea.z * 32 + lane]);
        float2 w2 = __half22float2(hh[eb.x * 32 + lane]);
        float2 w3 = __half22float2(hh[eb.z * 32 + lane]);
        ax += c0w * fmaxf(fmaf(w0.x, sc0, sh0), 0.f);
        ay += c0w * fmaxf(fmaf(w0.y, sc1, sh1), 0.f);
        bx += c1w * fmaxf(fmaf(w1.x, sc0, sh0), 0.f);
        by += c1w * fmaxf(fmaf(w1.y, sc1, sh1), 0.f);
        ax += c2w * fmaxf(fmaf(w2.x, sc0, sh0), 0.f);
        ay += c2w * fmaxf(fmaf(w2.y, sc1, sh1), 0.f);
        bx += c3w * fmaxf(fmaf(w3.x, sc0, sh0), 0.f);
        by += c3w * fmaxf(fmaf(w3.y, sc1, sh1), 0.f);
    }
    out[node * 32 + lane] = __floats2half2_rn(ax + bx, ay + by);
}

// D=16 over raw x with fused input-BN affine. 4 nodes/warp, 8 lanes/node.
__global__ void k_agg16p(const float* __restrict__ x, const float* __restrict__ bng,
                         const float* __restrict__ bnb, float* __restrict__ out) {
    int t = blockIdx.x * blockDim.x + threadIdx.x;
    int warp = t >> 5, lane = t & 31;
    int node = warp * 4 + (lane >> 3);
    int fl = lane & 7;
    if (node >= NN) return;
    const float invn = 1.0f / NN;
    int c0 = 2 * fl, c1 = 2 * fl + 1;
    float m0 = g_stats_in[c0] * invn, m1 = g_stats_in[c1] * invn;
    float v0 = g_stats_in[IND + c0] * invn - m0 * m0;
    float v1 = g_stats_in[IND + c1] * invn - m1 * m1;
    float sc0 = bng[c0] * rsqrtf(v0 + BN_EPS), sc1 = bng[c1] * rsqrtf(v1 + BN_EPS);
    float sh0 = bnb[c0] - m0 * sc0, sh1 = bnb[c1] - m1 * sc1;

    const float2* __restrict__ h2 = (const float2*)x;
    float di = g_dis[node];
    float2 hv = h2[node * 8 + fl];
    float ax = di * di * fmaf(hv.x, sc0, sh0);
    float ay = di * di * fmaf(hv.y, sc1, sh1);
    float bx = 0.f, by = 0.f;
    int s = g_rowptr[node], e = g_rowptr[node + 1];
    for (int p = s; p < e; p += 4) {
        int4 ea = *(const int4*)&g_ecw[p];
        int4 eb = *(const int4*)&g_ecw[p + 2];
        float c0w = __int_as_float(ea.y), c1w = __int_as_float(ea.w);
        float c2w = __int_as_float(eb.y), c3w = __int_as_float(eb.w);
        float2 w0 = h2[ea.x * 8 + fl];
        float2 w1 = h2[ea.z * 8 + fl];
        float2 w2 = h2[eb.x * 8 + fl];
        float2 w3 = h2[eb.z * 8 + fl];
        ax += c0w * fmaf(w0.x, sc0, sh0);
        ay += c0w * fmaf(w0.y, sc1, sh1);
        bx += c1w * fmaf(w1.x, sc0, sh0);
        by += c1w * fmaf(w1.y, sc1, sh1);
        ax += c2w * fmaf(w2.x, sc0, sh0);
        ay += c2w * fmaf(w2.y, sc1, sh1);
        bx += c3w * fmaf(w3.x, sc0, sh0);
        by += c3w * fmaf(w3.y, sc1, sh1);
    }
    ((float2*)out)[node * 8 + fl] = make_float2(ax + bx, ay + by);
}

// ---------------- dense matmul 16->64 (fp32 in, half out) -------------------
__global__ void k_mm16(const float* __restrict__ A, const float* __restrict__ W,
                       const float* __restrict__ b, __half* __restrict__ outh) {
    __shared__ __align__(16) float sW[IND * HD];
    __shared__ __align__(16) float sB[HD];
    for (int t = threadIdx.x; t < IND * HD; t += blockDim.x) sW[t] = W[t];
    for (int t = threadIdx.x; t < HD; t += blockDim.x) sB[t] = b[t];
    __syncthreads();
    int row = blockIdx.x * blockDim.x + threadIdx.x;
    if (row >= NN) return;
    unsigned long long acc[HD / 2];
    #pragma unroll
    for (int c = 0; c < HD / 2; c++)
        acc[c] = *(const unsigned long long*)&sB[2 * c];
    const float4* A4 = (const float4*)(A + row * IND);
    #pragma unroll
    for (int k0 = 0; k0 < IND; k0 += 4) {
        float4 a4 = A4[k0 / 4];
        float av[4] = {a4.x, a4.y, a4.z, a4.w};
        #pragma unroll
        for (int kk = 0; kk < 4; kk++) {
            unsigned long long xx = pack2(av[kk], av[kk]);
            const unsigned long long* wr =
                (const unsigned long long*)&sW[(k0 + kk) * HD];
            #pragma unroll
            for (int c = 0; c < HD / 2; c++) fma2(acc[c], xx, wr[c]);
        }
    }
    unsigned long long* o8 = (unsigned long long*)(outh + row * HD);
    #pragma unroll
    for (int c = 0; c < HD / 4; c++) {
        unsigned u0 = h2u(lo32(acc[2 * c]), hi32(acc[2 * c]));
        unsigned u1 = h2u(lo32(acc[2 * c + 1]), hi32(acc[2 * c + 1]));
        o8[c] = ((unsigned long long)u1 << 32) | u0;
    }
}

// ---------------- dense matmul 64->64 (half2 in, half out) ------------------
__global__ void k_mmh(const __half2* __restrict__ A, const float* __restrict__ W,
                      const float* __restrict__ b, __half* __restrict__ outh) {
    __shared__ __align__(16) float sW[HD * HD];
    __shared__ __align__(16) float sB[HD];
    for (int t = threadIdx.x; t < HD * HD; t += blockDim.x) sW[t] = W[t];
    for (int t = threadIdx.x; t < HD; t += blockDim.x) sB[t] = b[t];
    __syncthreads();
    int row = blockIdx.x * blockDim.x + threadIdx.x;
    if (row >= NN) return;
    unsigned long long acc[HD / 2];
    #pragma unroll
    for (int c = 0; c < HD / 2; c++)
        acc[c] = *(const unsigned long long*)&sB[2 * c];
    const uint4* A4 = (const uint4*)(A + row * 32);   // 8 halves per uint4
    #pragma unroll
    for (int k0 = 0; k0 < HD; k0 += 8) {
        uint4 q = A4[k0 / 8];
        unsigned u[4] = {q.x, q.y, q.z, q.w};
        #pragma unroll
        for (int m = 0; m < 4; m++) {
            float2 f = __half22float2(*(__half2*)&u[m]);
            unsigned long long xx0 = pack2(f.x, f.x);
            const unsigned long long* wr0 =
                (const unsigned long long*)&sW[(k0 + 2 * m) * HD];
            #pragma unroll
            for (int c = 0; c < HD / 2; c++) fma2(acc[c], xx0, wr0[c]);
            unsigned long long xx1 = pack2(f.y, f.y);
            const unsigned long long* wr1 =
                (const unsigned long long*)&sW[(k0 + 2 * m + 1) * HD];
            #pragma unroll
            for (int c = 0; c < HD / 2; c++) fma2(acc[c], xx1, wr1[c]);
        }
    }
    unsigned long long* o8 = (unsigned long long*)(outh + row * HD);
    #pragma unroll
    for (int c = 0; c < HD / 4; c++) {
        unsigned u0 = h2u(lo32(acc[2 * c]), hi32(acc[2 * c]));
        unsigned u1 = h2u(lo32(acc[2 * c + 1]), hi32(acc[2 * c + 1]));
        o8[c] = ((unsigned long long)u1 << 32) | u0;
    }
}

// ---------------- global mean pool (half2 input, fused BN+ReLU) -------------
__global__ void k_pool(const __half2* __restrict__ hh, const float* __restrict__ stats,
                       const float* __restrict__ g, const float* __restrict__ be,
                       const int* __restrict__ bid) {
    int t = blockIdx.x * blockDim.x + threadIdx.x;
    int w = t >> 5, lane = t & 31;
    int base = w * 8;
    if (base >= NN) return;
    const float invn = 1.0f / NN;
    int c0 = 2 * lane, c1 = 2 * lane + 1;
    float m0 = stats[c0] * invn, m1 = stats[c1] * invn;
    float v0 = stats[HD + c0] * invn - m0 * m0;
    float v1 = stats[HD + c1] * invn - m1 * m1;
    float sc0 = g[c0] * rsqrtf(v0 + BN_EPS), sc1 = g[c1] * rsqrtf(v1 + BN_EPS);
    float sh0 = be[c0] - m0 * sc0, sh1 = be[c1] - m1 * sc1;

    float2 acc = make_float2(0.f, 0.f);
    int cur = -1, cnt = 0;
    for (int k = 0; k < 8; k++) {
        int i = base + k;
        if (i >= NN) break;
        int gr = bid[i];
        if (gr != cur) {
            if (cur >= 0) {
                atomicAdd(&g_pool[cur * HD + c0], acc.x);
                atomicAdd(&g_pool[cur * HD + c1], acc.y);
                if (lane == 0) atomicAdd(&g_pcnt[cur], cnt);
            }
            cur = gr; acc = make_float2(0.f, 0.f); cnt = 0;
        }
        float2 v = __half22float2(hh[i * 32 + lane]);
        acc.x += fmaxf(fmaf(v.x, sc0, sh0), 0.f);
        acc.y += fmaxf(fmaf(v.y, sc1, sh1), 0.f);
        cnt++;
    }
    if (cur >= 0) {
        atomicAdd(&g_pool[cur * HD + c0], acc.x);
        atomicAdd(&g_pool[cur * HD + c1], acc.y);
        if (lane == 0) atomicAdd(&g_pcnt[cur], cnt);
    }
}

// ---------------- classifier head ------------------------------------------
__global__ void k_head(const float* __restrict__ Wc1, const float* __restrict__ bc1,
                       const float* __restrict__ Wc2, const float* __restrict__ bc2,
                       float* __restrict__ out) {
    __shared__ float sW[HD * HD];
    __shared__ float sb1[HD];
    __shared__ float sW2[HD * 2];
    __shared__ float sb2[2];
    for (int t = threadIdx.x; t < HD * HD; t += blockDim.x) sW[t] = Wc1[t];
    for (int t = threadIdx.x; t < HD; t += blockDim.x) sb1[t] = bc1[t];
    for (int t = threadIdx.x; t < HD * 2; t += blockDim.x) sW2[t] = Wc2[t];
    if (threadIdx.x < 2) sb2[threadIdx.x] = bc2[threadIdx.x];
    __syncthreads();
    int g = blockIdx.x * blockDim.x + threadIdx.x;
    if (g >= GG) return;
    float cnt = fmaxf((float)g_pcnt[g], 1.0f);
    float inv = 1.0f / cnt;
    float p[HD];
    #pragma unroll
    for (int f = 0; f < HD; f++) p[f] = g_pool[g * HD + f] * inv;
    float o0 = sb2[0], o1 = sb2[1];
    #pragma unroll 8
    for (int c = 0; c < HD; c++) {
        float z = sb1[c];
        #pragma unroll
        for (int k = 0; k < HD; k++) z += p[k] * sW[k * HD + c];
        z = fmaxf(z, 0.f);
        o0 += z * sW2[c * 2];
        o1 += z * sW2[c * 2 + 1];
    }
    out[g * 2] = o0;
    out[g * 2 + 1] = o1;
}

// ---------------- launch ----------------------------------------------------
extern "C" void kernel_launch(void* const* d_in, const int* in_sizes, int n_in,
                              void* d_out, int out_size) {
    const float *x, *bng, *bnb, *W0, *b0, *g0, *be0, *W1, *b1, *g1, *be1;
    const float *W2, *b2, *g2, *be2, *Wc1, *bc1, *Wc2, *bc2;
    const int *ei, *bid;

    if (in_sizes[1] == 2 * EE) {
        x   = (const float*)d_in[0];  ei  = (const int*)d_in[1];  bid = (const int*)d_in[2];
        bng = (const float*)d_in[3];  bnb = (const float*)d_in[4];
        W0  = (const float*)d_in[5];  b0  = (const float*)d_in[6];
        g0  = (const float*)d_in[7];  be0 = (const float*)d_in[8];
        W1  = (const float*)d_in[9];  b1  = (const float*)d_in[10];
        g1  = (const float*)d_in[11]; be1 = (const float*)d_in[12];
        W2  = (const float*)d_in[13]; b2  = (const float*)d_in[14];
        g2  = (const float*)d_in[15]; be2 = (const float*)d_in[16];
        Wc1 = (const float*)d_in[17]; bc1 = (const float*)d_in[18];
        Wc2 = (const float*)d_in[19]; bc2 = (const float*)d_in[20];
    } else {
        x   = (const float*)d_in[0];
        bng = (const float*)d_in[1];  bnb = (const float*)d_in[2];
        W0  = (const float*)d_in[3];  b0  = (const float*)d_in[4];
        g0  = (const float*)d_in[5];  be0 = (const float*)d_in[6];
        W1  = (const float*)d_in[7];  b1  = (const float*)d_in[8];
        g1  = (const float*)d_in[9];  be1 = (const float*)d_in[10];
        W2  = (const float*)d_in[11]; b2  = (const float*)d_in[12];
        g2  = (const float*)d_in[13]; be2 = (const float*)d_in[14];
        Wc1 = (const float*)d_in[15]; bc1 = (const float*)d_in[16];
        Wc2 = (const float*)d_in[17]; bc2 = (const float*)d_in[18];
        ei  = (const int*)d_in[19];   bid = (const int*)d_in[20];
    }

    float *a16, *st;
    __half *H;
    cudaGetSymbolAddress((void**)&a16, g_agg16);
    cudaGetSymbolAddress((void**)&H, g_H);
    cudaGetSymbolAddress((void**)&st, g_stats);
    __half *H0 = H, *H1 = H + NN * HD, *Ht = H + 2 * NN * HD;
    float *S1 = st, *S2 = st + 128, *S3 = st + 256;
    float* out = (float*)d_out;

    const int nb_scan1 = (NN + 511) / 512;
    const int nb_n = (NN + 255) / 256;
    const int nb_edge = (EE / 4 + 255) / 256;
    const int nb_agg64 = (NN * 32 + 255) / 256;
    const int nb_agg16 = (((NN + 3) / 4) * 32 + 255) / 256;
    const int nb_mm = (NN + 127) / 128;
    const int nb_pool = (((NN + 7) / 8) * 32 + 255) / 256;

    // ---- graph build + input stats ----
    k_init<<<256, 256>>>();                               // 0
    k_deg<<<nb_edge, 256>>>(ei);                          // 1
    k_scan1<<<nb_scan1, 512>>>();                         // 2  (also computes dis)
    k_stats_in<<<256, 256>>>(x);                          // 3  <- ncu capture
    k_scan2<<<1, 256>>>(nb_scan1);                        // 4
    k_scan3<<<nb_n, 256>>>();                             // 5  (also zeroes pad slots)
    k_fill<<<nb_edge, 256>>>(ei);                         // 6  (no atomics)

    // ---- layer 0 (16 -> 64): agg over BN(x), mm -> H0, stats ----
    k_agg16p<<<nb_agg16, 256>>>(x, bng, bnb, a16);        // 7
    k_mm16<<<nb_mm, 128>>>(a16, W0, b0, H0);              // 8
    k_cstats<<<256, 256>>>((const __half2*)H0, S1);       // 9

    // ---- layer 1 (64 -> 64): gather fp16, agg fp32 -> half, mm half-in ----
    k_agg64<<<nb_agg64, 256>>>((const __half2*)H0, S1, g0, be0, (__half2*)Ht); // 10
    k_mmh<<<nb_mm, 128>>>((const __half2*)Ht, W1, b1, H1);                     // 11
    k_cstats<<<256, 256>>>((const __half2*)H1, S2);                            // 12

    // ---- layer 2 (64 -> 64) ----
    k_agg64<<<nb_agg64, 256>>>((const __half2*)H1, S2, g1, be1, (__half2*)Ht); // 13
    k_mmh<<<nb_mm, 128>>>((const __half2*)Ht, W2, b2, H0);                     // 14
    k_cstats<<<256, 256>>>((const __half2*)H0, S3);                            // 15

    // ---- pool (applies BN2+relu) + head ----
    k_pool<<<nb_pool, 256>>>((const __half2*)H0, S3, g2, be2, bid);    // 16
    k_head<<<(GG + 63) / 64, 64>>>(Wc1, bc1, Wc2, bc2, out);           // 17
}